// round 3
// baseline (speedup 1.0000x reference)
#include <cuda_runtime.h>
#include <math.h>

// ---------------- problem constants ----------------
#define T_LEN 1024
#define HID   2048
#define NH    12
#define DK    128
#define DV    256
#define KDIM  (NH*DK)   // 1536
#define VDIM  (NH*DV)   // 3072

// ---------------- scratch (device global, no allocation) ----------------
// floats: qp,kp (1024x1536), vp,gp (1024x3072), q,k (1024x1536), v (1024x3072),
//         o,on (1024x3072), g,beta (1024x12)
#define SZ_K   (T_LEN*KDIM)       // 1572864
#define SZ_V   (T_LEN*VDIM)       // 3145728
#define SZ_H   (T_LEN*NH)         // 12288

#define OFF_QP 0
#define OFF_KP (OFF_QP + SZ_K)
#define OFF_VP (OFF_KP + SZ_K)
#define OFF_GP (OFF_VP + SZ_V)
#define OFF_Q  (OFF_GP + SZ_V)
#define OFF_K  (OFF_Q  + SZ_K)
#define OFF_V  (OFF_K  + SZ_K)
#define OFF_O  (OFF_V  + SZ_V)
#define OFF_ON (OFF_O  + SZ_V)
#define OFF_G  (OFF_ON + SZ_V)
#define OFF_B  (OFF_G  + SZ_H)
#define SCRATCH_TOTAL (OFF_B + SZ_H)

__device__ float g_scratch[SCRATCH_TOTAL];

// ---------------- generic fp32 SGEMM, up to 4 (B,C,N) per launch via z ----------------
// C = A[M,K] @ B[K,N], all row-major. BM=BN=128, BK=8, 256 threads, 8x8/thread.
__global__ __launch_bounds__(256) void sgemm4(
    const float* __restrict__ A, int M, int K,
    const float* __restrict__ B0, float* __restrict__ C0, int N0,
    const float* __restrict__ B1, float* __restrict__ C1, int N1,
    const float* __restrict__ B2, float* __restrict__ C2, int N2,
    const float* __restrict__ B3, float* __restrict__ C3, int N3)
{
    const float* B; float* C; int N;
    switch (blockIdx.z) {
        case 0:  B = B0; C = C0; N = N0; break;
        case 1:  B = B1; C = C1; N = N1; break;
        case 2:  B = B2; C = C2; N = N2; break;
        default: B = B3; C = C3; N = N3; break;
    }
    int bn = blockIdx.x * 128;
    if (bn >= N) return;
    int bm = blockIdx.y * 128;

    __shared__ float As[8][128];
    __shared__ float Bs[8][128];

    int tid  = threadIdx.x;
    int aRow = tid >> 1;            // 0..127
    int aCol = (tid & 1) << 2;      // 0 or 4
    int bRow = tid >> 5;            // 0..7
    int bCol = (tid & 31) << 2;     // 0..124
    int tx   = tid & 15;
    int ty   = tid >> 4;

    float acc[8][8];
    #pragma unroll
    for (int i = 0; i < 8; i++)
        #pragma unroll
        for (int j = 0; j < 8; j++) acc[i][j] = 0.f;

    const float* Aptr = A + (size_t)(bm + aRow) * K + aCol;
    const float* Bptr = B + (size_t)bRow * N + bn + bCol;

    for (int k0 = 0; k0 < K; k0 += 8) {
        float4 av = *(const float4*)Aptr; Aptr += 8;
        As[aCol+0][aRow] = av.x;
        As[aCol+1][aRow] = av.y;
        As[aCol+2][aRow] = av.z;
        As[aCol+3][aRow] = av.w;
        float4 bv = *(const float4*)Bptr; Bptr += (size_t)8 * N;
        *(float4*)&Bs[bRow][bCol] = bv;
        __syncthreads();

        #pragma unroll
        for (int kk = 0; kk < 8; kk++) {
            float ar[8], br[8];
            #pragma unroll
            for (int i = 0; i < 8; i++) ar[i] = As[kk][ty*8+i];
            #pragma unroll
            for (int j = 0; j < 8; j++) br[j] = Bs[kk][tx*8+j];
            #pragma unroll
            for (int i = 0; i < 8; i++)
                #pragma unroll
                for (int j = 0; j < 8; j++)
                    acc[i][j] = fmaf(ar[i], br[j], acc[i][j]);
        }
        __syncthreads();
    }

    #pragma unroll
    for (int i = 0; i < 8; i++) {
        float* crow = C + (size_t)(bm + ty*8 + i) * N + bn + tx*8;
        *(float4*)(crow)     = make_float4(acc[i][0], acc[i][1], acc[i][2], acc[i][3]);
        *(float4*)(crow + 4) = make_float4(acc[i][4], acc[i][5], acc[i][6], acc[i][7]);
    }
}

// ---------------- beta / g projection (N=12 each) ----------------
__global__ __launch_bounds__(256) void beta_g_kernel(
    const float* __restrict__ hs,
    const float* __restrict__ Wb, const float* __restrict__ Wa,
    const float* __restrict__ A_log, const float* __restrict__ dt_bias,
    float* __restrict__ beta, float* __restrict__ gout)
{
    int t = blockIdx.x;
    int warp = threadIdx.x >> 5, lane = threadIdx.x & 31;
    const float* h = hs + (size_t)t * HID;
    #pragma unroll
    for (int r = 0; r < 3; r++) {
        int idx = warp * 3 + r;            // 0..23
        int is_b = (idx < NH);
        int hh = is_b ? idx : idx - NH;
        const float* W = is_b ? Wb : Wa;
        float s = 0.f;
        for (int kk = lane; kk < HID; kk += 32)
            s = fmaf(h[kk], W[(size_t)kk * NH + hh], s);
        #pragma unroll
        for (int off = 16; off; off >>= 1)
            s += __shfl_xor_sync(0xffffffffu, s, off);
        if (lane == 0) {
            if (is_b) {
                beta[t*NH + hh] = 1.f / (1.f + expf(-s));
            } else {
                float x = s + dt_bias[hh];
                float sp = (x > 20.f) ? x : log1pf(expf(x));
                gout[t*NH + hh] = -expf(A_log[hh]) * sp;
            }
        }
    }
}

// ---------------- causal depthwise conv (K=4) + SiLU + per-head L2 norm (q,k) ----------------
__global__ __launch_bounds__(128) void conv_norm_qk(
    const float* __restrict__ qp, const float* __restrict__ kp,
    const float* __restrict__ wq, const float* __restrict__ wk,
    float* __restrict__ qo, float* __restrict__ ko)
{
    int t = blockIdx.x, h = blockIdx.y, which = blockIdx.z;
    const float* src = which ? kp : qp;
    const float* w   = which ? wk : wq;
    float* dst       = which ? ko : qo;

    int c = h * DK + threadIdx.x;
    float y = 0.f;
    #pragma unroll
    for (int i = 0; i < 4; i++) {
        int tt = t - 3 + i;
        if (tt >= 0) y = fmaf(src[(size_t)tt * KDIM + c], w[c*4 + i], y);
    }
    y = y / (1.f + expf(-y));          // SiLU

    float ss = y * y;
    #pragma unroll
    for (int off = 16; off; off >>= 1)
        ss += __shfl_xor_sync(0xffffffffu, ss, off);
    __shared__ float red[4];
    int lane = threadIdx.x & 31, warp = threadIdx.x >> 5;
    if (lane == 0) red[warp] = ss;
    __syncthreads();
    float tot = red[0] + red[1] + red[2] + red[3];
    dst[(size_t)t * KDIM + c] = y * rsqrtf(tot + 1e-6f);
}

// ---------------- causal depthwise conv (K=4) + SiLU for v (no norm) ----------------
__global__ __launch_bounds__(256) void conv_v_kernel(
    const float* __restrict__ vp, const float* __restrict__ wv, float* __restrict__ vo)
{
    int idx = blockIdx.x * 256 + threadIdx.x;   // 0 .. T*VDIM-1
    int c = idx % VDIM, t = idx / VDIM;
    float y = 0.f;
    #pragma unroll
    for (int i = 0; i < 4; i++) {
        int tt = t - 3 + i;
        if (tt >= 0) y = fmaf(vp[(size_t)tt * VDIM + c], wv[c*4 + i], y);
    }
    vo[idx] = y / (1.f + expf(-y));
}

// ---------------- gated delta-rule scan ----------------
// 96 CTAs = 12 heads x 8 chunks of 32 DV columns. 256 threads: j = tid&31 (column),
// kg = tid>>5 (warp id == k-group of 16 rows). State S[16] per thread in registers.
__global__ __launch_bounds__(256) void scan_kernel(
    const float* __restrict__ q, const float* __restrict__ k,
    const float* __restrict__ v, const float* __restrict__ gg,
    const float* __restrict__ bb, float* __restrict__ o)
{
    int h     = blockIdx.x >> 3;
    int chunk = blockIdx.x & 7;
    int tid = threadIdx.x;
    int j  = tid & 31;
    int kg = tid >> 5;            // == warp id (0..7)

    __shared__ float ksh[128], qsh[128], vsh[32], dsh[32];
    __shared__ float pd[8][32];
    __shared__ float gb[2];

    float S[16];
    #pragma unroll
    for (int i = 0; i < 16; i++) S[i] = 0.f;

    const int kq_base = h * DK;
    const int v_base  = h * DV + chunk * 32;

    for (int t = 0; t < T_LEN; t++) {
        // stage inputs for this step
        if (tid < 128) ksh[tid]       = k[(size_t)t * KDIM + kq_base + tid];
        else           qsh[tid - 128] = q[(size_t)t * KDIM + kq_base + (tid - 128)];
        if (tid < 32)  vsh[tid] = v[(size_t)t * VDIM + v_base + tid];
        if (tid == 32) gb[0] = gg[t*NH + h];
        if (tid == 33) gb[1] = bb[t*NH + h];
        __syncthreads();                                   // (A)

        float eg = expf(gb[0]);

        // partial dot  (k . S_old) over my 16 k-rows
        float p = 0.f;
        #pragma unroll
        for (int i = 0; i < 16; i++) p = fmaf(ksh[kg*16 + i], S[i], p);
        pd[kg][j] = p;
        __syncthreads();                                   // (B)

        if (kg == 0) {
            float kS = 0.f;
            #pragma unroll
            for (int g2 = 0; g2 < 8; g2++) kS += pd[g2][j];
            // delta_j = (v_j - k . (eg*S_old)) * beta
            dsh[j] = (vsh[j] - eg * kS) * gb[1];
        }
        __syncthreads();                                   // (C)

        float d = dsh[j];
        float qa = 0.f;
        #pragma unroll
        for (int i = 0; i < 16; i++) {
            float s = fmaf(S[i], eg, ksh[kg*16 + i] * d);  // S_new = eg*S_old + k*delta
            S[i] = s;
            qa = fmaf(qsh[kg*16 + i], s, qa);              // o_j partial = q . S_new
        }
        pd[kg][j] = qa;
        __syncthreads();                                   // (D)

        if (kg == 0) {
            float os = 0.f;
            #pragma unroll
            for (int g2 = 0; g2 < 8; g2++) os += pd[g2][j];
            o[(size_t)t * VDIM + v_base + j] = os;
        }
        // pd for t+1 is only written after barrier (A) of t+1, which kg0 must also pass.
    }
}

// ---------------- RMSNorm * norm_w * SiLU(gate) ----------------
__global__ __launch_bounds__(256) void epilogue_kernel(
    const float* __restrict__ o, const float* __restrict__ gp,
    const float* __restrict__ norm_w, float* __restrict__ on)
{
    int t = blockIdx.x, h = blockIdx.y;
    int d = threadIdx.x;
    size_t idx = (size_t)t * VDIM + h * DV + d;
    float x = o[idx];

    float ss = x * x;
    #pragma unroll
    for (int off = 16; off; off >>= 1)
        ss += __shfl_xor_sync(0xffffffffu, ss, off);
    __shared__ float red[8];
    int lane = threadIdx.x & 31, warp = threadIdx.x >> 5;
    if (lane == 0) red[warp] = ss;
    __syncthreads();
    float tot = 0.f;
    #pragma unroll
    for (int w = 0; w < 8; w++) tot += red[w];

    float scale = rsqrtf(tot * (1.f / 256.f) + 1e-5f);
    float g = gp[idx];
    float silu_g = g / (1.f + expf(-g));
    on[idx] = x * scale * norm_w[d] * silu_g;
}

// ---------------- launch ----------------
extern "C" void kernel_launch(void* const* d_in, const int* in_sizes, int n_in,
                              void* d_out, int out_size)
{
    const float* hs      = (const float*)d_in[0];
    const float* Wq      = (const float*)d_in[1];
    const float* Wk      = (const float*)d_in[2];
    const float* Wv      = (const float*)d_in[3];
    const float* Wb      = (const float*)d_in[4];
    const float* Wa      = (const float*)d_in[5];
    const float* Wg      = (const float*)d_in[6];
    const float* Wo      = (const float*)d_in[7];
    const float* conv_wq = (const float*)d_in[8];
    const float* conv_wk = (const float*)d_in[9];
    const float* conv_wv = (const float*)d_in[10];
    const float* A_log   = (const float*)d_in[11];
    const float* dt_bias = (const float*)d_in[12];
    const float* norm_w  = (const float*)d_in[13];
    float* out = (float*)d_out;

    float* s = nullptr;
    cudaGetSymbolAddress((void**)&s, g_scratch);
    float* qp   = s + OFF_QP;
    float* kp   = s + OFF_KP;
    float* vp   = s + OFF_VP;
    float* gp   = s + OFF_GP;
    float* qb   = s + OFF_Q;
    float* kb   = s + OFF_K;
    float* vb   = s + OFF_V;
    float* ob   = s + OFF_O;
    float* onb  = s + OFF_ON;
    float* gbuf = s + OFF_G;
    float* bbuf = s + OFF_B;

    // 1) fused projections: qp,kp (N=1536), vp,gp (N=3072)
    sgemm4<<<dim3(24, 8, 4), 256>>>(hs, T_LEN, HID,
                                    Wq, qp, KDIM,
                                    Wk, kp, KDIM,
                                    Wv, vp, VDIM,
                                    Wg, gp, VDIM);
    // 2) beta / g
    beta_g_kernel<<<T_LEN, 256>>>(hs, Wb, Wa, A_log, dt_bias, bbuf, gbuf);
    // 3) conv + silu + l2norm for q,k
    conv_norm_qk<<<dim3(T_LEN, NH, 2), 128>>>(qp, kp, conv_wq, conv_wk, qb, kb);
    // 4) conv + silu for v
    conv_v_kernel<<<(T_LEN * VDIM) / 256, 256>>>(vp, conv_wv, vb);
    // 5) sequential gated delta scan
    scan_kernel<<<NH * 8, 256>>>(qb, kb, vb, gbuf, bbuf, ob);
    // 6) rmsnorm * swish-gate
    epilogue_kernel<<<dim3(T_LEN, NH), 256>>>(ob, gp, norm_w, onb);
    // 7) output projection
    sgemm4<<<dim3(16, 8, 1), 256>>>(onb, T_LEN, VDIM,
                                    Wo, out, HID,
                                    nullptr, nullptr, 0,
                                    nullptr, nullptr, 0,
                                    nullptr, nullptr, 0);
}

// round 5
// speedup vs baseline: 1.5229x; 1.5229x over previous
#include <cuda_runtime.h>
#include <cuda_bf16.h>
#include <math.h>
#include <stdint.h>

// ---------------- problem constants ----------------
#define T_LEN 1024
#define HID   2048
#define NH    12
#define DK    128
#define DV    256
#define KDIM  1536         // NH*DK
#define VDIM  3072         // NH*DV
#define PROJN 9216         // q(1536) k(1536) v(3072) g(3072)
#define K3    6144         // 3*HID   (split-K for projection GEMM, bf16)
#define K3O   9216         // 3*VDIM  (split-K for output GEMM, bf16)

// ---------------- scratch (device global; byte offsets) ----------------
#define B_PROJ 0u                              // f32 [1024][9216]
#define B_A3   (B_PROJ + 37748736u)            // bf16 [1024][6144]
#define B_B3   (B_A3   + 12582912u)            // bf16 [9216][6144]
#define B_A2   (B_B3   + 113246208u)           // bf16 [1024][9216]
#define B_B2   (B_A2   + 18874368u)            // bf16 [2048][9216]
#define B_Q    (B_B2   + 37748736u)            // f32 [1024][1536]
#define B_K    (B_Q    + 6291456u)
#define B_V    (B_K    + 6291456u)             // f32 [1024][3072]
#define B_O    (B_V    + 12582912u)
#define B_G    (B_O    + 12582912u)            // f32 [1024][12]
#define B_BB   (B_G    + 49152u)
#define SCRATCH_BYTES (B_BB + 49152u)

__device__ __align__(256) unsigned char g_scratch[SCRATCH_BYTES];

// ---------------- PTX helpers (all plain-target: sm_80-class) ----------------
__device__ __forceinline__ uint32_t smem_u32(const void* p) {
    uint32_t a;
    asm("{ .reg .u64 t; cvta.to.shared.u64 t, %1; cvt.u32.u64 %0, t; }" : "=r"(a) : "l"(p));
    return a;
}
__device__ __forceinline__ void cpasync16(uint32_t dst, const void* src) {
    asm volatile("cp.async.cg.shared.global [%0], [%1], 16;" :: "r"(dst), "l"(src) : "memory");
}
#define CP_COMMIT() asm volatile("cp.async.commit_group;" ::: "memory")
#define CP_WAIT1()  asm volatile("cp.async.wait_group 1;" ::: "memory")

__device__ __forceinline__ void ldm4(uint32_t* r, uint32_t addr) {
    asm volatile("ldmatrix.sync.aligned.m8n8.x4.shared.b16 {%0,%1,%2,%3}, [%4];"
        : "=r"(r[0]), "=r"(r[1]), "=r"(r[2]), "=r"(r[3]) : "r"(addr));
}
__device__ __forceinline__ void mma16816(float* c, const uint32_t* a, uint32_t b0, uint32_t b1) {
    asm volatile("mma.sync.aligned.m16n8k16.row.col.f32.bf16.bf16.f32 "
        "{%0,%1,%2,%3}, {%4,%5,%6,%7}, {%8,%9}, {%0,%1,%2,%3};"
        : "+f"(c[0]), "+f"(c[1]), "+f"(c[2]), "+f"(c[3])
        : "r"(a[0]), "r"(a[1]), "r"(a[2]), "r"(a[3]), "r"(b0), "r"(b1));
}
#define SWZ128(o) ((o) ^ (((o) >> 3) & 0x70))

// ---------------- bf16 mma.sync GEMM: C[M,N] = A[M,K] @ Bt[N,K]^T ----------------
// CTA tile 128x128, BK=64 (128B rows, SW128 swizzle), cp.async double buffer,
// 8 warps each 32(M)x64(N), mma m16n8k16 bf16 -> f32.
#define GEMM_SMEM 65536

__global__ __launch_bounds__(256, 2) void gemm_bf16(
    const __nv_bfloat16* __restrict__ A, const __nv_bfloat16* __restrict__ Bt,
    float* __restrict__ C, int M, int N, int K)
{
    extern __shared__ unsigned char smem_raw[];
    uint32_t sb = smem_u32(smem_raw);
    // layout: buf p (p=0,1): A tile at p*32768, B tile at p*32768 + 16384

    const int tid  = threadIdx.x;
    const int wid  = tid >> 5;
    const int lane = tid & 31;
    const int wm   = wid & 3;      // warp M block (x32)
    const int wn   = wid >> 2;     // warp N block (x64)

    const int bm = blockIdx.x * 128;
    const int bn = blockIdx.y * 128;

    // cp.async staging: 2 threads per row, 64B each
    const int lrow = tid >> 1;
    const int lcol = (tid & 1) * 64;               // byte offset within 128B row
    const unsigned char* Ag = (const unsigned char*)(A + (size_t)(bm + lrow) * K) + lcol;
    const unsigned char* Bg = (const unsigned char*)(Bt + (size_t)(bn + lrow) * K) + lcol;
    uint32_t st[4];
#pragma unroll
    for (int j = 0; j < 4; j++) {
        uint32_t o = (uint32_t)lrow * 128u + (uint32_t)lcol + j * 16u;
        st[j] = SWZ128(o);
    }

    // ldmatrix lane addressing (offsets within tile, pre-swizzled by construction)
    const int l8 = lane & 7;
    const int rowA = wm * 32 + ((lane >> 3) & 1) * 8 + l8;
    const uint32_t colA = (uint32_t)((lane >> 4) * 16);
    const uint32_t xorA = (uint32_t)((rowA & 7) << 4);
    const int rowB = wn * 64 + ((lane >> 4) & 1) * 8 + l8;
    const uint32_t colB = (uint32_t)(((lane >> 3) & 1) * 16);
    const uint32_t xorB = (uint32_t)((rowB & 7) << 4);

    float c[2][8][4];
#pragma unroll
    for (int mf = 0; mf < 2; mf++)
#pragma unroll
        for (int nf = 0; nf < 8; nf++)
#pragma unroll
            for (int i = 0; i < 4; i++) c[mf][nf][i] = 0.f;

    const int chunks = K >> 6;

    // prologue: chunks 0 and 1
#pragma unroll
    for (int p = 0; p < 2; p++) {
        uint32_t ab = sb + p * 32768u;
        uint32_t bb = ab + 16384u;
#pragma unroll
        for (int j = 0; j < 4; j++) cpasync16(ab + st[j], Ag + j * 16);
#pragma unroll
        for (int j = 0; j < 4; j++) cpasync16(bb + st[j], Bg + j * 16);
        Ag += 128; Bg += 128;
        CP_COMMIT();
    }

    for (int i = 0; i < chunks; i++) {
        CP_WAIT1();
        __syncthreads();
        uint32_t ab = sb + (uint32_t)(i & 1) * 32768u;
        uint32_t bb = ab + 16384u;

#pragma unroll
        for (int ks = 0; ks < 4; ks++) {
            uint32_t af0[4], af1[4];
            uint32_t ac = ((uint32_t)(ks * 32) + colA) ^ xorA;
            ldm4(af0, ab + (uint32_t)rowA * 128u + ac);
            ldm4(af1, ab + (uint32_t)rowA * 128u + 2048u + ac);   // +16 rows

            uint32_t bf[4][4];
            uint32_t bc = ((uint32_t)(ks * 32) + colB) ^ xorB;
#pragma unroll
            for (int p = 0; p < 4; p++)
                ldm4(bf[p], bb + (uint32_t)(rowB + p * 16) * 128u + bc);

#pragma unroll
            for (int nf = 0; nf < 8; nf++) {
                uint32_t b0 = bf[nf >> 1][(nf & 1) * 2 + 0];
                uint32_t b1 = bf[nf >> 1][(nf & 1) * 2 + 1];
                mma16816(c[0][nf], af0, b0, b1);
                mma16816(c[1][nf], af1, b0, b1);
            }
        }
        __syncthreads();

        if (i + 2 < chunks) {
            uint32_t ab2 = sb + (uint32_t)(i & 1) * 32768u;
            uint32_t bb2 = ab2 + 16384u;
#pragma unroll
            for (int j = 0; j < 4; j++) cpasync16(ab2 + st[j], Ag + j * 16);
#pragma unroll
            for (int j = 0; j < 4; j++) cpasync16(bb2 + st[j], Bg + j * 16);
            Ag += 128; Bg += 128;
        }
        CP_COMMIT();   // always commit (possibly empty) to keep group accounting uniform
    }

    // epilogue
    const int g  = lane >> 2;
    const int t4 = lane & 3;
#pragma unroll
    for (int mf = 0; mf < 2; mf++) {
#pragma unroll
        for (int nf = 0; nf < 8; nf++) {
            int row = bm + wm * 32 + mf * 16 + g;
            int col = bn + wn * 64 + nf * 8 + t4 * 2;
            float2 v0 = make_float2(c[mf][nf][0], c[mf][nf][1]);
            float2 v1 = make_float2(c[mf][nf][2], c[mf][nf][3]);
            *(float2*)(C + (size_t)row * N + col)        = v0;
            *(float2*)(C + (size_t)(row + 8) * N + col)  = v1;
        }
    }
}

// ---------------- bf16 hi/lo split helpers ----------------
__device__ __forceinline__ void bf16split(float x, __nv_bfloat16& hi, __nv_bfloat16& lo) {
    hi = __float2bfloat16_rn(x);
    lo = __float2bfloat16_rn(x - __bfloat162float(hi));
}

// ---------------- split hs -> A3 bf16 [hi | lo | hi] ----------------
__global__ __launch_bounds__(256) void split_hs(const float* __restrict__ hs, __nv_bfloat16* __restrict__ A3)
{
    int idx = blockIdx.x * 256 + threadIdx.x;  // T*HID
    int t = idx >> 11, k = idx & 2047;
    __nv_bfloat16 hi, lo;
    bf16split(hs[idx], hi, lo);
    __nv_bfloat16* row = A3 + (size_t)t * K3;
    row[k] = hi; row[HID + k] = lo; row[2 * HID + k] = hi;
}

// ---------------- transpose+split proj weights -> B3 bf16 [PROJN][K3] = [hi | hi | lo] ----------------
__global__ __launch_bounds__(256) void tsplit_proj(
    const float* __restrict__ Wq, const float* __restrict__ Wk,
    const float* __restrict__ Wv, const float* __restrict__ Wg,
    __nv_bfloat16* __restrict__ B3)
{
    __shared__ float tile[32][33];
    int k0 = blockIdx.x * 32, n0 = blockIdx.y * 32;
    int tx = threadIdx.x & 31, ty = threadIdx.x >> 5;
#pragma unroll
    for (int i = 0; i < 4; i++) {
        int k = k0 + ty + i * 8, n = n0 + tx;
        float v;
        if      (n < KDIM)            v = Wq[(size_t)k * KDIM + n];
        else if (n < 2 * KDIM)        v = Wk[(size_t)k * KDIM + n - KDIM];
        else if (n < 2 * KDIM + VDIM) v = Wv[(size_t)k * VDIM + n - 2 * KDIM];
        else                          v = Wg[(size_t)k * VDIM + n - 2 * KDIM - VDIM];
        tile[ty + i * 8][tx] = v;
    }
    __syncthreads();
#pragma unroll
    for (int i = 0; i < 4; i++) {
        int n = n0 + ty + i * 8, k = k0 + tx;
        __nv_bfloat16 hi, lo;
        bf16split(tile[tx][ty + i * 8], hi, lo);
        __nv_bfloat16* row = B3 + (size_t)n * K3;
        row[k] = hi; row[HID + k] = hi; row[2 * HID + k] = lo;
    }
}

// ---------------- transpose+split Wo -> B2 bf16 [HID][K3O] = [hi | hi | lo] ----------------
__global__ __launch_bounds__(256) void tsplit_wo(const float* __restrict__ Wo, __nv_bfloat16* __restrict__ B2)
{
    __shared__ float tile[32][33];
    int k0 = blockIdx.x * 32, n0 = blockIdx.y * 32;   // k over VDIM, n over HID
    int tx = threadIdx.x & 31, ty = threadIdx.x >> 5;
#pragma unroll
    for (int i = 0; i < 4; i++) {
        int k = k0 + ty + i * 8, n = n0 + tx;
        tile[ty + i * 8][tx] = Wo[(size_t)k * HID + n];
    }
    __syncthreads();
#pragma unroll
    for (int i = 0; i < 4; i++) {
        int n = n0 + ty + i * 8, k = k0 + tx;
        __nv_bfloat16 hi, lo;
        bf16split(tile[tx][ty + i * 8], hi, lo);
        __nv_bfloat16* row = B2 + (size_t)n * K3O;
        row[k] = hi; row[VDIM + k] = hi; row[2 * VDIM + k] = lo;
    }
}

// ---------------- beta / g projection (N=12 each) ----------------
__global__ __launch_bounds__(256) void beta_g_kernel(
    const float* __restrict__ hs,
    const float* __restrict__ Wb, const float* __restrict__ Wa,
    const float* __restrict__ A_log, const float* __restrict__ dt_bias,
    float* __restrict__ beta, float* __restrict__ gout)
{
    int t = blockIdx.x;
    int warp = threadIdx.x >> 5, lane = threadIdx.x & 31;
    const float* h = hs + (size_t)t * HID;
#pragma unroll
    for (int r = 0; r < 3; r++) {
        int idx = warp * 3 + r;
        int is_b = (idx < NH);
        int hh = is_b ? idx : idx - NH;
        const float* W = is_b ? Wb : Wa;
        float s = 0.f;
        for (int kk = lane; kk < HID; kk += 32)
            s = fmaf(h[kk], W[(size_t)kk * NH + hh], s);
#pragma unroll
        for (int off = 16; off; off >>= 1)
            s += __shfl_xor_sync(0xffffffffu, s, off);
        if (lane == 0) {
            if (is_b) {
                beta[t * NH + hh] = 1.f / (1.f + expf(-s));
            } else {
                float x = s + dt_bias[hh];
                float sp = (x > 20.f) ? x : log1pf(expf(x));
                gout[t * NH + hh] = -expf(A_log[hh]) * sp;
            }
        }
    }
}

// ---------------- conv (K=4) + SiLU + per-head L2 norm for q,k ----------------
__global__ __launch_bounds__(128) void conv_norm_qk(
    const float* __restrict__ proj,
    const float* __restrict__ wq, const float* __restrict__ wk,
    float* __restrict__ qo, float* __restrict__ ko)
{
    int t = blockIdx.x, h = blockIdx.y, which = blockIdx.z;
    int colbase = which ? KDIM : 0;
    const float* w = which ? wk : wq;
    float* dst = which ? ko : qo;

    int c = h * DK + threadIdx.x;
    float y = 0.f;
#pragma unroll
    for (int i = 0; i < 4; i++) {
        int tt = t - 3 + i;
        if (tt >= 0) y = fmaf(proj[(size_t)tt * PROJN + colbase + c], w[c * 4 + i], y);
    }
    y = y / (1.f + expf(-y));

    float ss = y * y;
#pragma unroll
    for (int off = 16; off; off >>= 1)
        ss += __shfl_xor_sync(0xffffffffu, ss, off);
    __shared__ float red[4];
    int lane = threadIdx.x & 31, warp = threadIdx.x >> 5;
    if (lane == 0) red[warp] = ss;
    __syncthreads();
    float tot = red[0] + red[1] + red[2] + red[3];
    dst[(size_t)t * KDIM + c] = y * rsqrtf(tot + 1e-6f);
}

// ---------------- conv (K=4) + SiLU for v ----------------
__global__ __launch_bounds__(256) void conv_v_kernel(
    const float* __restrict__ proj, const float* __restrict__ wv, float* __restrict__ vo)
{
    int idx = blockIdx.x * 256 + threadIdx.x;   // T*VDIM
    int c = idx % VDIM, t = idx / VDIM;
    float y = 0.f;
#pragma unroll
    for (int i = 0; i < 4; i++) {
        int tt = t - 3 + i;
        if (tt >= 0) y = fmaf(proj[(size_t)tt * PROJN + 2 * KDIM + c], wv[c * 4 + i], y);
    }
    vo[idx] = y / (1.f + expf(-y));
}

// ---------------- gated delta-rule scan (96 CTAs, 3 barriers/step) ----------------
__global__ __launch_bounds__(256) void scan_kernel(
    const float* __restrict__ q, const float* __restrict__ k,
    const float* __restrict__ v, const float* __restrict__ gg,
    const float* __restrict__ bb, float* __restrict__ o)
{
    int h = blockIdx.x >> 3;
    int chunk = blockIdx.x & 7;
    int tid = threadIdx.x;
    int j = tid & 31;
    int kg = tid >> 5;

    __shared__ float ksh[128], qsh[128], vsh[32];
    __shared__ float pd[8][32], pd2[8][32];
    __shared__ float gb[2];

    float S[16];
#pragma unroll
    for (int i = 0; i < 16; i++) S[i] = 0.f;

    const int kq_base = h * DK;
    const int v_base = h * DV + chunk * 32;

    for (int t = 0; t < T_LEN; t++) {
        if (tid < 128) ksh[tid]       = k[(size_t)t * KDIM + kq_base + tid];
        else           qsh[tid - 128] = q[(size_t)t * KDIM + kq_base + (tid - 128)];
        if (tid < 32)  vsh[tid] = v[(size_t)t * VDIM + v_base + tid];
        if (tid == 32) gb[0] = gg[t * NH + h];
        if (tid == 33) gb[1] = bb[t * NH + h];
        __syncthreads();                                    // (A)

        float eg = expf(gb[0]);
        float bet = gb[1];

        float p = 0.f;
#pragma unroll
        for (int i = 0; i < 16; i++) p = fmaf(ksh[kg * 16 + i], S[i], p);
        pd[kg][j] = p;
        __syncthreads();                                    // (B)

        float kS = 0.f;
#pragma unroll
        for (int g2 = 0; g2 < 8; g2++) kS += pd[g2][j];
        float d = (vsh[j] - eg * kS) * bet;

        float qa = 0.f;
#pragma unroll
        for (int i = 0; i < 16; i++) {
            float sv = fmaf(S[i], eg, ksh[kg * 16 + i] * d);
            S[i] = sv;
            qa = fmaf(qsh[kg * 16 + i], sv, qa);
        }
        pd2[kg][j] = qa;
        __syncthreads();                                    // (D)

        if (kg == 0) {
            float os = 0.f;
#pragma unroll
            for (int g2 = 0; g2 < 8; g2++) os += pd2[g2][j];
            o[(size_t)t * VDIM + v_base + j] = os;
        }
    }
}

// ---------------- RMSNorm * norm_w * SiLU(gate), fused bf16 split -> A2 [hi | lo | hi] ----------------
__global__ __launch_bounds__(256) void epilogue_kernel(
    const float* __restrict__ o, const float* __restrict__ proj,
    const float* __restrict__ norm_w, __nv_bfloat16* __restrict__ A2)
{
    int t = blockIdx.x, h = blockIdx.y;
    int d = threadIdx.x;
    float x = o[(size_t)t * VDIM + h * DV + d];

    float ss = x * x;
#pragma unroll
    for (int off = 16; off; off >>= 1)
        ss += __shfl_xor_sync(0xffffffffu, ss, off);
    __shared__ float red[8];
    int lane = threadIdx.x & 31, warp = threadIdx.x >> 5;
    if (lane == 0) red[warp] = ss;
    __syncthreads();
    float tot = 0.f;
#pragma unroll
    for (int w = 0; w < 8; w++) tot += red[w];

    float scale = rsqrtf(tot * (1.f / 256.f) + 1e-5f);
    float g = proj[(size_t)t * PROJN + 2 * KDIM + VDIM + h * DV + d];
    float silu_g = g / (1.f + expf(-g));
    float val = x * scale * norm_w[d] * silu_g;

    __nv_bfloat16 hi, lo;
    bf16split(val, hi, lo);
    __nv_bfloat16* row = A2 + (size_t)t * K3O;
    int col = h * DV + d;
    row[col] = hi; row[VDIM + col] = lo; row[2 * VDIM + col] = hi;
}

// ---------------- launch ----------------
extern "C" void kernel_launch(void* const* d_in, const int* in_sizes, int n_in,
                              void* d_out, int out_size)
{
    const float* hs      = (const float*)d_in[0];
    const float* Wq      = (const float*)d_in[1];
    const float* Wk      = (const float*)d_in[2];
    const float* Wv      = (const float*)d_in[3];
    const float* Wb      = (const float*)d_in[4];
    const float* Wa      = (const float*)d_in[5];
    const float* Wg      = (const float*)d_in[6];
    const float* Wo      = (const float*)d_in[7];
    const float* conv_wq = (const float*)d_in[8];
    const float* conv_wk = (const float*)d_in[9];
    const float* conv_wv = (const float*)d_in[10];
    const float* A_log   = (const float*)d_in[11];
    const float* dt_bias = (const float*)d_in[12];
    const float* norm_w  = (const float*)d_in[13];
    float* out = (float*)d_out;

    unsigned char* s = nullptr;
    cudaGetSymbolAddress((void**)&s, g_scratch);
    float*          PROJ = (float*)(s + B_PROJ);
    __nv_bfloat16*  A3   = (__nv_bfloat16*)(s + B_A3);
    __nv_bfloat16*  B3   = (__nv_bfloat16*)(s + B_B3);
    __nv_bfloat16*  A2   = (__nv_bfloat16*)(s + B_A2);
    __nv_bfloat16*  B2   = (__nv_bfloat16*)(s + B_B2);
    float*          Qb   = (float*)(s + B_Q);
    float*          Kb   = (float*)(s + B_K);
    float*          Vb   = (float*)(s + B_V);
    float*          Ob   = (float*)(s + B_O);
    float*          Gb   = (float*)(s + B_G);
    float*          Bb   = (float*)(s + B_BB);

    cudaFuncSetAttribute(gemm_bf16, cudaFuncAttributeMaxDynamicSharedMemorySize, GEMM_SMEM);

    // 1) bf16 hi/lo splits
    split_hs<<<(T_LEN * HID) / 256, 256>>>(hs, A3);
    tsplit_proj<<<dim3(HID / 32, PROJN / 32), 256>>>(Wq, Wk, Wv, Wg, B3);
    tsplit_wo<<<dim3(VDIM / 32, HID / 32), 256>>>(Wo, B2);

    // 2) fused projection GEMM: PROJ[1024,9216] = A3 @ B3^T
    gemm_bf16<<<dim3(T_LEN / 128, PROJN / 128), 256, GEMM_SMEM>>>(A3, B3, PROJ, T_LEN, PROJN, K3);

    // 3) beta / g
    beta_g_kernel<<<T_LEN, 256>>>(hs, Wb, Wa, A_log, dt_bias, Bb, Gb);
    // 4) conv + silu (+ l2norm for q,k)
    conv_norm_qk<<<dim3(T_LEN, NH, 2), 128>>>(PROJ, conv_wq, conv_wk, Qb, Kb);
    conv_v_kernel<<<(T_LEN * VDIM) / 256, 256>>>(PROJ, conv_wv, Vb);
    // 5) sequential gated delta scan
    scan_kernel<<<NH * 8, 256>>>(Qb, Kb, Vb, Gb, Bb, Ob);
    // 6) rmsnorm * swish-gate, fused split into A2
    epilogue_kernel<<<dim3(T_LEN, NH), 256>>>(Ob, PROJ, norm_w, A2);
    // 7) output GEMM: out[1024,2048] = A2 @ B2^T
    gemm_bf16<<<dim3(T_LEN / 128, HID / 128), 256, GEMM_SMEM>>>(A2, B2, out, T_LEN, HID, K3O);
}

// round 6
// speedup vs baseline: 2.0093x; 1.3193x over previous
#include <cuda_runtime.h>
#include <cuda_bf16.h>
#include <math.h>
#include <stdint.h>

// ---------------- problem constants ----------------
#define T_LEN 1024
#define HID   2048
#define NH    12
#define DK    128
#define DV    256
#define KDIM  1536         // NH*DK
#define VDIM  3072         // NH*DV
#define PROJN 9216         // q(1536) k(1536) v(3072) g(3072)
#define PROJN_PAD 9344     // + beta(12) + a(12) + zero-pad to x128
#define K3    6144         // 3*HID   (split-K for projection GEMM, bf16)
#define K3O   9216         // 3*VDIM  (split-K for output GEMM, bf16)

// ---------------- scratch (device global) ----------------
constexpr size_t SZ_PROJ = (size_t)T_LEN * PROJN_PAD * 4;      // f32
constexpr size_t SZ_A3   = (size_t)T_LEN * K3 * 2;             // bf16
constexpr size_t SZ_B3   = (size_t)PROJN_PAD * K3 * 2;         // bf16
constexpr size_t SZ_A2   = (size_t)T_LEN * K3O * 2;            // bf16
constexpr size_t SZ_B2   = (size_t)HID * K3O * 2;              // bf16
constexpr size_t SZ_QK   = (size_t)T_LEN * KDIM * 4;           // f32
constexpr size_t SZ_V    = (size_t)T_LEN * VDIM * 4;           // f32
constexpr size_t SZ_H    = (size_t)T_LEN * NH * 4;             // f32

constexpr size_t B_PROJ = 0;
constexpr size_t B_A3   = B_PROJ + SZ_PROJ;
constexpr size_t B_B3   = B_A3 + SZ_A3;
constexpr size_t B_A2   = B_B3 + SZ_B3;
constexpr size_t B_B2   = B_A2 + SZ_A2;
constexpr size_t B_Q    = B_B2 + SZ_B2;
constexpr size_t B_K    = B_Q + SZ_QK;
constexpr size_t B_V    = B_K + SZ_QK;
constexpr size_t B_O    = B_V + SZ_V;
constexpr size_t B_G    = B_O + SZ_V;
constexpr size_t B_BB   = B_G + SZ_H;
constexpr size_t SCRATCH_BYTES = B_BB + SZ_H;

__device__ __align__(256) unsigned char g_scratch[SCRATCH_BYTES];

// ---------------- PTX helpers (plain-target, sm_80-class) ----------------
__device__ __forceinline__ uint32_t smem_u32(const void* p) {
    uint32_t a;
    asm("{ .reg .u64 t; cvta.to.shared.u64 t, %1; cvt.u32.u64 %0, t; }" : "=r"(a) : "l"(p));
    return a;
}
__device__ __forceinline__ void cpasync16(uint32_t dst, const void* src) {
    asm volatile("cp.async.cg.shared.global [%0], [%1], 16;" :: "r"(dst), "l"(src) : "memory");
}
#define CP_COMMIT() asm volatile("cp.async.commit_group;" ::: "memory")
#define CP_WAIT1()  asm volatile("cp.async.wait_group 1;" ::: "memory")

__device__ __forceinline__ void ldm4(uint32_t* r, uint32_t addr) {
    asm volatile("ldmatrix.sync.aligned.m8n8.x4.shared.b16 {%0,%1,%2,%3}, [%4];"
        : "=r"(r[0]), "=r"(r[1]), "=r"(r[2]), "=r"(r[3]) : "r"(addr));
}
__device__ __forceinline__ void mma16816(float* c, const uint32_t* a, uint32_t b0, uint32_t b1) {
    asm volatile("mma.sync.aligned.m16n8k16.row.col.f32.bf16.bf16.f32 "
        "{%0,%1,%2,%3}, {%4,%5,%6,%7}, {%8,%9}, {%0,%1,%2,%3};"
        : "+f"(c[0]), "+f"(c[1]), "+f"(c[2]), "+f"(c[3])
        : "r"(a[0]), "r"(a[1]), "r"(a[2]), "r"(a[3]), "r"(b0), "r"(b1));
}
#define SWZ128(o) ((o) ^ (((o) >> 3) & 0x70))

// ---------------- bf16 mma.sync GEMM: C[M,N] = A[M,K] @ Bt[N,K]^T ----------------
// CTA tile 128x128, BK=64, SW128 swizzle, 3-stage cp.async pipeline,
// 8 warps each 32(M)x64(N), mma m16n8k16 bf16 -> f32.
#define GEMM_SMEM 98304

__global__ __launch_bounds__(256, 2) void gemm_bf16(
    const __nv_bfloat16* __restrict__ A, const __nv_bfloat16* __restrict__ Bt,
    float* __restrict__ C, int M, int N, int K)
{
    extern __shared__ unsigned char smem_raw[];
    uint32_t sb = smem_u32(smem_raw);
    // stage s: A tile at s*32768, B tile at s*32768 + 16384 ; 3 stages

    const int tid  = threadIdx.x;
    const int wid  = tid >> 5;
    const int lane = tid & 31;
    const int wm   = wid & 3;      // warp M block (x32)
    const int wn   = wid >> 2;     // warp N block (x64)

    const int bm = blockIdx.x * 128;
    const int bn = blockIdx.y * 128;

    // cp.async staging: 2 threads per row, 64B each
    const int lrow = tid >> 1;
    const int lcol = (tid & 1) * 64;
    const unsigned char* Ag = (const unsigned char*)(A + (size_t)(bm + lrow) * K) + lcol;
    const unsigned char* Bg = (const unsigned char*)(Bt + (size_t)(bn + lrow) * K) + lcol;
    uint32_t st[4];
#pragma unroll
    for (int j = 0; j < 4; j++) {
        uint32_t o = (uint32_t)lrow * 128u + (uint32_t)lcol + j * 16u;
        st[j] = SWZ128(o);
    }

    // ldmatrix lane addressing
    const int l8 = lane & 7;
    const int rowA = wm * 32 + ((lane >> 3) & 1) * 8 + l8;
    const uint32_t colA = (uint32_t)((lane >> 4) * 16);
    const uint32_t xorA = (uint32_t)((rowA & 7) << 4);
    const int rowB = wn * 64 + ((lane >> 4) & 1) * 8 + l8;
    const uint32_t colB = (uint32_t)(((lane >> 3) & 1) * 16);
    const uint32_t xorB = (uint32_t)((rowB & 7) << 4);

    float c[2][8][4];
#pragma unroll
    for (int mf = 0; mf < 2; mf++)
#pragma unroll
        for (int nf = 0; nf < 8; nf++)
#pragma unroll
            for (int i = 0; i < 4; i++) c[mf][nf][i] = 0.f;

    const int chunks = K >> 6;

    // prologue: chunks 0,1 into stages 0,1
#pragma unroll
    for (int p = 0; p < 2; p++) {
        uint32_t ab = sb + (uint32_t)p * 32768u;
        uint32_t bb = ab + 16384u;
#pragma unroll
        for (int j = 0; j < 4; j++) cpasync16(ab + st[j], Ag + j * 16);
#pragma unroll
        for (int j = 0; j < 4; j++) cpasync16(bb + st[j], Bg + j * 16);
        Ag += 128; Bg += 128;
        CP_COMMIT();
    }

    int sc = 0;   // stage of chunk i
    int sp = 2;   // stage of chunk i+2

    for (int i = 0; i < chunks; i++) {
        CP_WAIT1();            // chunk i landed
        __syncthreads();       // all warps done with compute of chunk i-1 (stage sp)

        if (i + 2 < chunks) {
            uint32_t ab2 = sb + (uint32_t)sp * 32768u;
            uint32_t bb2 = ab2 + 16384u;
#pragma unroll
            for (int j = 0; j < 4; j++) cpasync16(ab2 + st[j], Ag + j * 16);
#pragma unroll
            for (int j = 0; j < 4; j++) cpasync16(bb2 + st[j], Bg + j * 16);
            Ag += 128; Bg += 128;
        }
        CP_COMMIT();

        uint32_t ab = sb + (uint32_t)sc * 32768u;
        uint32_t bb = ab + 16384u;
#pragma unroll
        for (int ks = 0; ks < 4; ks++) {
            uint32_t af0[4], af1[4];
            uint32_t ac = ((uint32_t)(ks * 32) + colA) ^ xorA;
            ldm4(af0, ab + (uint32_t)rowA * 128u + ac);
            ldm4(af1, ab + (uint32_t)rowA * 128u + 2048u + ac);

            uint32_t bf[4][4];
            uint32_t bc = ((uint32_t)(ks * 32) + colB) ^ xorB;
#pragma unroll
            for (int p = 0; p < 4; p++)
                ldm4(bf[p], bb + (uint32_t)(rowB + p * 16) * 128u + bc);

#pragma unroll
            for (int nf = 0; nf < 8; nf++) {
                uint32_t b0 = bf[nf >> 1][(nf & 1) * 2 + 0];
                uint32_t b1 = bf[nf >> 1][(nf & 1) * 2 + 1];
                mma16816(c[0][nf], af0, b0, b1);
                mma16816(c[1][nf], af1, b0, b1);
            }
        }

        sc = (sc == 2) ? 0 : sc + 1;
        sp = (sp == 2) ? 0 : sp + 1;
    }

    // epilogue
    const int g  = lane >> 2;
    const int t4 = lane & 3;
#pragma unroll
    for (int mf = 0; mf < 2; mf++) {
#pragma unroll
        for (int nf = 0; nf < 8; nf++) {
            int row = bm + wm * 32 + mf * 16 + g;
            int col = bn + wn * 64 + nf * 8 + t4 * 2;
            *(float2*)(C + (size_t)row * N + col)       = make_float2(c[mf][nf][0], c[mf][nf][1]);
            *(float2*)(C + (size_t)(row + 8) * N + col) = make_float2(c[mf][nf][2], c[mf][nf][3]);
        }
    }
}

// ---------------- bf16 hi/lo split ----------------
__device__ __forceinline__ void bf16split(float x, __nv_bfloat16& hi, __nv_bfloat16& lo) {
    hi = __float2bfloat16_rn(x);
    lo = __float2bfloat16_rn(x - __bfloat162float(hi));
}

// ---------------- split hs -> A3 bf16 [hi | lo | hi] ----------------
__global__ __launch_bounds__(256) void split_hs(const float* __restrict__ hs, __nv_bfloat16* __restrict__ A3)
{
    int idx = blockIdx.x * 256 + threadIdx.x;  // T*HID
    int t = idx >> 11, k = idx & 2047;
    __nv_bfloat16 hi, lo;
    bf16split(hs[idx], hi, lo);
    __nv_bfloat16* row = A3 + (size_t)t * K3;
    row[k] = hi; row[HID + k] = lo; row[2 * HID + k] = hi;
}

// ---------------- transpose+split proj weights -> B3 bf16 [PROJN_PAD][K3] = [hi | hi | lo] ----------------
__global__ __launch_bounds__(256) void tsplit_proj(
    const float* __restrict__ Wq, const float* __restrict__ Wk,
    const float* __restrict__ Wv, const float* __restrict__ Wg,
    const float* __restrict__ Wb, const float* __restrict__ Wa,
    __nv_bfloat16* __restrict__ B3)
{
    __shared__ float tile[32][33];
    int k0 = blockIdx.x * 32, n0 = blockIdx.y * 32;
    int tx = threadIdx.x & 31, ty = threadIdx.x >> 5;
#pragma unroll
    for (int i = 0; i < 4; i++) {
        int k = k0 + ty + i * 8, n = n0 + tx;
        float v;
        if      (n < KDIM)            v = Wq[(size_t)k * KDIM + n];
        else if (n < 2 * KDIM)        v = Wk[(size_t)k * KDIM + n - KDIM];
        else if (n < 2 * KDIM + VDIM) v = Wv[(size_t)k * VDIM + n - 2 * KDIM];
        else if (n < PROJN)           v = Wg[(size_t)k * VDIM + n - 2 * KDIM - VDIM];
        else if (n < PROJN + NH)      v = Wb[(size_t)k * NH + n - PROJN];
        else if (n < PROJN + 2 * NH)  v = Wa[(size_t)k * NH + n - PROJN - NH];
        else                          v = 0.f;
        tile[ty + i * 8][tx] = v;
    }
    __syncthreads();
#pragma unroll
    for (int i = 0; i < 4; i++) {
        int n = n0 + ty + i * 8, k = k0 + tx;
        __nv_bfloat16 hi, lo;
        bf16split(tile[tx][ty + i * 8], hi, lo);
        __nv_bfloat16* row = B3 + (size_t)n * K3;
        row[k] = hi; row[HID + k] = hi; row[2 * HID + k] = lo;
    }
}

// ---------------- transpose+split Wo -> B2 bf16 [HID][K3O] = [hi | hi | lo] ----------------
__global__ __launch_bounds__(256) void tsplit_wo(const float* __restrict__ Wo, __nv_bfloat16* __restrict__ B2)
{
    __shared__ float tile[32][33];
    int k0 = blockIdx.x * 32, n0 = blockIdx.y * 32;   // k over VDIM, n over HID
    int tx = threadIdx.x & 31, ty = threadIdx.x >> 5;
#pragma unroll
    for (int i = 0; i < 4; i++) {
        int k = k0 + ty + i * 8, n = n0 + tx;
        tile[ty + i * 8][tx] = Wo[(size_t)k * HID + n];
    }
    __syncthreads();
#pragma unroll
    for (int i = 0; i < 4; i++) {
        int n = n0 + ty + i * 8, k = k0 + tx;
        __nv_bfloat16 hi, lo;
        bf16split(tile[tx][ty + i * 8], hi, lo);
        __nv_bfloat16* row = B2 + (size_t)n * K3O;
        row[k] = hi; row[VDIM + k] = hi; row[2 * VDIM + k] = lo;
    }
}

// ---------------- beta / g: activations on GEMM-computed columns ----------------
__global__ __launch_bounds__(256) void beta_g_finish(
    const float* __restrict__ proj,
    const float* __restrict__ A_log, const float* __restrict__ dt_bias,
    float* __restrict__ beta, float* __restrict__ gout)
{
    int idx = blockIdx.x * 256 + threadIdx.x;   // T*24
    if (idx >= T_LEN * 24) return;
    int t = idx / 24, c = idx % 24;
    float sv = proj[(size_t)t * PROJN_PAD + PROJN + c];
    if (c < NH) {
        beta[t * NH + c] = 1.f / (1.f + expf(-sv));
    } else {
        int hh = c - NH;
        float x = sv + dt_bias[hh];
        float sp = (x > 20.f) ? x : log1pf(expf(x));
        gout[t * NH + hh] = -expf(A_log[hh]) * sp;
    }
}

// ---------------- conv (K=4) + SiLU + per-head L2 norm for q,k ----------------
__global__ __launch_bounds__(128) void conv_norm_qk(
    const float* __restrict__ proj,
    const float* __restrict__ wq, const float* __restrict__ wk,
    float* __restrict__ qo, float* __restrict__ ko)
{
    int t = blockIdx.x, h = blockIdx.y, which = blockIdx.z;
    int colbase = which ? KDIM : 0;
    const float* w = which ? wk : wq;
    float* dst = which ? ko : qo;

    int c = h * DK + threadIdx.x;
    float y = 0.f;
#pragma unroll
    for (int i = 0; i < 4; i++) {
        int tt = t - 3 + i;
        if (tt >= 0) y = fmaf(proj[(size_t)tt * PROJN_PAD + colbase + c], w[c * 4 + i], y);
    }
    y = y / (1.f + expf(-y));

    float ss = y * y;
#pragma unroll
    for (int off = 16; off; off >>= 1)
        ss += __shfl_xor_sync(0xffffffffu, ss, off);
    __shared__ float red[4];
    int lane = threadIdx.x & 31, warp = threadIdx.x >> 5;
    if (lane == 0) red[warp] = ss;
    __syncthreads();
    float tot = red[0] + red[1] + red[2] + red[3];
    dst[(size_t)t * KDIM + c] = y * rsqrtf(tot + 1e-6f);
}

// ---------------- conv (K=4) + SiLU for v ----------------
__global__ __launch_bounds__(256) void conv_v_kernel(
    const float* __restrict__ proj, const float* __restrict__ wv, float* __restrict__ vo)
{
    int idx = blockIdx.x * 256 + threadIdx.x;   // T*VDIM
    int c = idx % VDIM, t = idx / VDIM;
    float y = 0.f;
#pragma unroll
    for (int i = 0; i < 4; i++) {
        int tt = t - 3 + i;
        if (tt >= 0) y = fmaf(proj[(size_t)tt * PROJN_PAD + 2 * KDIM + c], wv[c * 4 + i], y);
    }
    vo[idx] = y / (1.f + expf(-y));
}

// ---------------- gated delta-rule scan (96 CTAs, register-prefetched) ----------------
__global__ __launch_bounds__(256) void scan_kernel(
    const float* __restrict__ q, const float* __restrict__ k,
    const float* __restrict__ v, const float* __restrict__ gg,
    const float* __restrict__ bb, float* __restrict__ o)
{
    int h = blockIdx.x >> 3;
    int chunk = blockIdx.x & 7;
    int tid = threadIdx.x;
    int j = tid & 31;
    int kg = tid >> 5;

    __shared__ float ksh[128], qsh[128], vsh[32];
    __shared__ float pd[8][32], pd2[8][32];
    __shared__ float gb[2];

    float S[16];
#pragma unroll
    for (int i = 0; i < 16; i++) S[i] = 0.f;

    const int kq_base = h * DK;
    const int v_base = h * DV + chunk * 32;

    // prefetch t=0
    float pk, pv = 0.f, pgb = 0.f;
    if (tid < 128) pk = k[kq_base + tid];
    else           pk = q[kq_base + tid - 128];
    if (tid < 32)  pv = v[v_base + tid];
    if (tid == 32) pgb = gg[h];
    if (tid == 33) pgb = bb[h];

    for (int t = 0; t < T_LEN; t++) {
        // stage prefetched values
        if (tid < 128) ksh[tid] = pk;
        else           qsh[tid - 128] = pk;
        if (tid < 32)  vsh[tid] = pv;
        if (tid == 32) gb[0] = pgb;
        if (tid == 33) gb[1] = pgb;
        __syncthreads();                                    // (A)

        // issue prefetch for t+1 (overlaps with compute below)
        if (t + 1 < T_LEN) {
            size_t r = (size_t)(t + 1);
            if (tid < 128) pk = k[r * KDIM + kq_base + tid];
            else           pk = q[r * KDIM + kq_base + tid - 128];
            if (tid < 32)  pv = v[r * VDIM + v_base + tid];
            if (tid == 32) pgb = gg[r * NH + h];
            if (tid == 33) pgb = bb[r * NH + h];
        }

        float eg = expf(gb[0]);
        float bet = gb[1];

        float p = 0.f;
#pragma unroll
        for (int i = 0; i < 16; i++) p = fmaf(ksh[kg * 16 + i], S[i], p);
        pd[kg][j] = p;
        __syncthreads();                                    // (B)

        float kS = 0.f;
#pragma unroll
        for (int g2 = 0; g2 < 8; g2++) kS += pd[g2][j];
        float d = (vsh[j] - eg * kS) * bet;

        float qa = 0.f;
#pragma unroll
        for (int i = 0; i < 16; i++) {
            float sv = fmaf(S[i], eg, ksh[kg * 16 + i] * d);
            S[i] = sv;
            qa = fmaf(qsh[kg * 16 + i], sv, qa);
        }
        pd2[kg][j] = qa;
        __syncthreads();                                    // (C)

        if (kg == 0) {
            float os = 0.f;
#pragma unroll
            for (int g2 = 0; g2 < 8; g2++) os += pd2[g2][j];
            o[(size_t)t * VDIM + v_base + j] = os;
        }
    }
}

// ---------------- RMSNorm * norm_w * SiLU(gate), fused bf16 split -> A2 [hi | lo | hi] ----------------
__global__ __launch_bounds__(256) void epilogue_kernel(
    const float* __restrict__ o, const float* __restrict__ proj,
    const float* __restrict__ norm_w, __nv_bfloat16* __restrict__ A2)
{
    int t = blockIdx.x, h = blockIdx.y;
    int d = threadIdx.x;
    float x = o[(size_t)t * VDIM + h * DV + d];

    float ss = x * x;
#pragma unroll
    for (int off = 16; off; off >>= 1)
        ss += __shfl_xor_sync(0xffffffffu, ss, off);
    __shared__ float red[8];
    int lane = threadIdx.x & 31, warp = threadIdx.x >> 5;
    if (lane == 0) red[warp] = ss;
    __syncthreads();
    float tot = 0.f;
#pragma unroll
    for (int w = 0; w < 8; w++) tot += red[w];

    float scale = rsqrtf(tot * (1.f / 256.f) + 1e-5f);
    float g = proj[(size_t)t * PROJN_PAD + 2 * KDIM + VDIM + h * DV + d];
    float silu_g = g / (1.f + expf(-g));
    float val = x * scale * norm_w[d] * silu_g;

    __nv_bfloat16 hi, lo;
    bf16split(val, hi, lo);
    __nv_bfloat16* row = A2 + (size_t)t * K3O;
    int col = h * DV + d;
    row[col] = hi; row[VDIM + col] = lo; row[2 * VDIM + col] = hi;
}

// ---------------- launch ----------------
extern "C" void kernel_launch(void* const* d_in, const int* in_sizes, int n_in,
                              void* d_out, int out_size)
{
    const float* hs      = (const float*)d_in[0];
    const float* Wq      = (const float*)d_in[1];
    const float* Wk      = (const float*)d_in[2];
    const float* Wv      = (const float*)d_in[3];
    const float* Wb      = (const float*)d_in[4];
    const float* Wa      = (const float*)d_in[5];
    const float* Wg      = (const float*)d_in[6];
    const float* Wo      = (const float*)d_in[7];
    const float* conv_wq = (const float*)d_in[8];
    const float* conv_wk = (const float*)d_in[9];
    const float* conv_wv = (const float*)d_in[10];
    const float* A_log   = (const float*)d_in[11];
    const float* dt_bias = (const float*)d_in[12];
    const float* norm_w  = (const float*)d_in[13];
    float* out = (float*)d_out;

    unsigned char* s = nullptr;
    cudaGetSymbolAddress((void**)&s, g_scratch);
    float*          PROJ = (float*)(s + B_PROJ);
    __nv_bfloat16*  A3   = (__nv_bfloat16*)(s + B_A3);
    __nv_bfloat16*  B3   = (__nv_bfloat16*)(s + B_B3);
    __nv_bfloat16*  A2   = (__nv_bfloat16*)(s + B_A2);
    __nv_bfloat16*  B2   = (__nv_bfloat16*)(s + B_B2);
    float*          Qb   = (float*)(s + B_Q);
    float*          Kb   = (float*)(s + B_K);
    float*          Vb   = (float*)(s + B_V);
    float*          Ob   = (float*)(s + B_O);
    float*          Gb   = (float*)(s + B_G);
    float*          Bb   = (float*)(s + B_BB);

    cudaFuncSetAttribute(gemm_bf16, cudaFuncAttributeMaxDynamicSharedMemorySize, GEMM_SMEM);

    // 1) bf16 hi/lo splits (beta/a weights folded into B3 padding columns)
    split_hs<<<(T_LEN * HID) / 256, 256>>>(hs, A3);
    tsplit_proj<<<dim3(HID / 32, PROJN_PAD / 32), 256>>>(Wq, Wk, Wv, Wg, Wb, Wa, B3);
    tsplit_wo<<<dim3(VDIM / 32, HID / 32), 256>>>(Wo, B2);

    // 2) fused projection GEMM: PROJ[1024,9344] = A3 @ B3^T
    gemm_bf16<<<dim3(T_LEN / 128, PROJN_PAD / 128), 256, GEMM_SMEM>>>(A3, B3, PROJ, T_LEN, PROJN_PAD, K3);

    // 3) beta / g activations
    beta_g_finish<<<(T_LEN * 24 + 255) / 256, 256>>>(PROJ, A_log, dt_bias, Bb, Gb);
    // 4) conv + silu (+ l2norm for q,k)
    conv_norm_qk<<<dim3(T_LEN, NH, 2), 128>>>(PROJ, conv_wq, conv_wk, Qb, Kb);
    conv_v_kernel<<<(T_LEN * VDIM) / 256, 256>>>(PROJ, conv_wv, Vb);
    // 5) sequential gated delta scan
    scan_kernel<<<NH * 8, 256>>>(Qb, Kb, Vb, Gb, Bb, Ob);
    // 6) rmsnorm * swish-gate, fused split into A2
    epilogue_kernel<<<dim3(T_LEN, NH), 256>>>(Ob, PROJ, norm_w, A2);
    // 7) output GEMM: out[1024,2048] = A2 @ B2^T
    gemm_bf16<<<dim3(T_LEN / 128, HID / 128), 256, GEMM_SMEM>>>(A2, B2, out, T_LEN, HID, K3O);
}

// round 7
// speedup vs baseline: 2.0165x; 1.0036x over previous
#include <cuda_runtime.h>
#include <cuda_bf16.h>
#include <math.h>
#include <stdint.h>

// ---------------- problem constants ----------------
#define T_LEN 1024
#define HID   2048
#define NH    12
#define DK    128
#define DV    256
#define KDIM  1536         // NH*DK
#define VDIM  3072         // NH*DV
#define PROJN 9216         // q(1536) k(1536) v(3072) g(3072)
#define PROJN_PAD 9344     // + beta(12) + a(12) + zero-pad to x128
#define K3    6144         // 3*HID   (split-K for projection GEMM, bf16)
#define K3O   9216         // 3*VDIM  (split-K for output GEMM, bf16)

// ---------------- scratch (device global) ----------------
constexpr size_t SZ_PROJ = (size_t)T_LEN * PROJN_PAD * 4;      // f32
constexpr size_t SZ_A3   = (size_t)T_LEN * K3 * 2;             // bf16
constexpr size_t SZ_B3   = (size_t)PROJN_PAD * K3 * 2;         // bf16 (reused as split-K partials later)
constexpr size_t SZ_A2   = (size_t)T_LEN * K3O * 2;            // bf16
constexpr size_t SZ_B2   = (size_t)HID * K3O * 2;              // bf16
constexpr size_t SZ_QK   = (size_t)T_LEN * KDIM * 4;           // f32
constexpr size_t SZ_V    = (size_t)T_LEN * VDIM * 4;           // f32
constexpr size_t SZ_H    = (size_t)T_LEN * NH * 4;             // f32

constexpr size_t B_PROJ = 0;
constexpr size_t B_A3   = B_PROJ + SZ_PROJ;
constexpr size_t B_B3   = B_A3 + SZ_A3;
constexpr size_t B_A2   = B_B3 + SZ_B3;
constexpr size_t B_B2   = B_A2 + SZ_A2;
constexpr size_t B_Q    = B_B2 + SZ_B2;
constexpr size_t B_K    = B_Q + SZ_QK;
constexpr size_t B_V    = B_K + SZ_QK;
constexpr size_t B_O    = B_V + SZ_V;
constexpr size_t B_G    = B_O + SZ_V;
constexpr size_t B_BB   = B_G + SZ_H;
constexpr size_t SCRATCH_BYTES = B_BB + SZ_H;

__device__ __align__(256) unsigned char g_scratch[SCRATCH_BYTES];

// ---------------- PTX helpers (plain-target, sm_80-class) ----------------
__device__ __forceinline__ uint32_t smem_u32(const void* p) {
    uint32_t a;
    asm("{ .reg .u64 t; cvta.to.shared.u64 t, %1; cvt.u32.u64 %0, t; }" : "=r"(a) : "l"(p));
    return a;
}
__device__ __forceinline__ void cpasync16(uint32_t dst, const void* src) {
    asm volatile("cp.async.cg.shared.global [%0], [%1], 16;" :: "r"(dst), "l"(src) : "memory");
}
#define CP_COMMIT() asm volatile("cp.async.commit_group;" ::: "memory")
#define CP_WAIT1()  asm volatile("cp.async.wait_group 1;" ::: "memory")

__device__ __forceinline__ void ldm4(uint32_t* r, uint32_t addr) {
    asm volatile("ldmatrix.sync.aligned.m8n8.x4.shared.b16 {%0,%1,%2,%3}, [%4];"
        : "=r"(r[0]), "=r"(r[1]), "=r"(r[2]), "=r"(r[3]) : "r"(addr));
}
__device__ __forceinline__ void mma16816(float* c, const uint32_t* a, uint32_t b0, uint32_t b1) {
    asm volatile("mma.sync.aligned.m16n8k16.row.col.f32.bf16.bf16.f32 "
        "{%0,%1,%2,%3}, {%4,%5,%6,%7}, {%8,%9}, {%0,%1,%2,%3};"
        : "+f"(c[0]), "+f"(c[1]), "+f"(c[2]), "+f"(c[3])
        : "r"(a[0]), "r"(a[1]), "r"(a[2]), "r"(a[3]), "r"(b0), "r"(b1));
}
#define SWZ128(o) ((o) ^ (((o) >> 3) & 0x70))

// ---------------- bf16 mma.sync GEMM with optional split-K via gridDim.z ----------------
// C_z[M,N] = A[M, kStart:kStart+kCount] @ Bt[N, kStart:kStart+kCount]^T,  kStart = z*kCount.
// Partial z writes to C + z*M*N. CTA tile 128x128, BK=64, 3-stage cp.async pipeline.
#define GEMM_SMEM 98304

__global__ __launch_bounds__(256, 2) void gemm_bf16(
    const __nv_bfloat16* __restrict__ A, const __nv_bfloat16* __restrict__ Bt,
    float* __restrict__ C, int M, int N, int K, int kCount)
{
    extern __shared__ unsigned char smem_raw[];
    uint32_t sb = smem_u32(smem_raw);

    const int tid  = threadIdx.x;
    const int wid  = tid >> 5;
    const int lane = tid & 31;
    const int wm   = wid & 3;
    const int wn   = wid >> 2;

    const int bm = blockIdx.x * 128;
    const int bn = blockIdx.y * 128;
    const int kStart = blockIdx.z * kCount;
    float* Cz = C + (size_t)blockIdx.z * M * N;

    const int lrow = tid >> 1;
    const int lcol = (tid & 1) * 64;
    const unsigned char* Ag = (const unsigned char*)(A + (size_t)(bm + lrow) * K + kStart) + lcol;
    const unsigned char* Bg = (const unsigned char*)(Bt + (size_t)(bn + lrow) * K + kStart) + lcol;
    uint32_t st[4];
#pragma unroll
    for (int j = 0; j < 4; j++) {
        uint32_t o = (uint32_t)lrow * 128u + (uint32_t)lcol + j * 16u;
        st[j] = SWZ128(o);
    }

    const int l8 = lane & 7;
    const int rowA = wm * 32 + ((lane >> 3) & 1) * 8 + l8;
    const uint32_t colA = (uint32_t)((lane >> 4) * 16);
    const uint32_t xorA = (uint32_t)((rowA & 7) << 4);
    const int rowB = wn * 64 + ((lane >> 4) & 1) * 8 + l8;
    const uint32_t colB = (uint32_t)(((lane >> 3) & 1) * 16);
    const uint32_t xorB = (uint32_t)((rowB & 7) << 4);

    float c[2][8][4];
#pragma unroll
    for (int mf = 0; mf < 2; mf++)
#pragma unroll
        for (int nf = 0; nf < 8; nf++)
#pragma unroll
            for (int i = 0; i < 4; i++) c[mf][nf][i] = 0.f;

    const int chunks = kCount >> 6;

#pragma unroll
    for (int p = 0; p < 2; p++) {
        uint32_t ab = sb + (uint32_t)p * 32768u;
        uint32_t bb = ab + 16384u;
#pragma unroll
        for (int j = 0; j < 4; j++) cpasync16(ab + st[j], Ag + j * 16);
#pragma unroll
        for (int j = 0; j < 4; j++) cpasync16(bb + st[j], Bg + j * 16);
        Ag += 128; Bg += 128;
        CP_COMMIT();
    }

    int sc = 0;
    int sp = 2;

    for (int i = 0; i < chunks; i++) {
        CP_WAIT1();
        __syncthreads();

        if (i + 2 < chunks) {
            uint32_t ab2 = sb + (uint32_t)sp * 32768u;
            uint32_t bb2 = ab2 + 16384u;
#pragma unroll
            for (int j = 0; j < 4; j++) cpasync16(ab2 + st[j], Ag + j * 16);
#pragma unroll
            for (int j = 0; j < 4; j++) cpasync16(bb2 + st[j], Bg + j * 16);
            Ag += 128; Bg += 128;
        }
        CP_COMMIT();

        uint32_t ab = sb + (uint32_t)sc * 32768u;
        uint32_t bb = ab + 16384u;
#pragma unroll
        for (int ks = 0; ks < 4; ks++) {
            uint32_t af0[4], af1[4];
            uint32_t ac = ((uint32_t)(ks * 32) + colA) ^ xorA;
            ldm4(af0, ab + (uint32_t)rowA * 128u + ac);
            ldm4(af1, ab + (uint32_t)rowA * 128u + 2048u + ac);

            uint32_t bf[4][4];
            uint32_t bc = ((uint32_t)(ks * 32) + colB) ^ xorB;
#pragma unroll
            for (int p = 0; p < 4; p++)
                ldm4(bf[p], bb + (uint32_t)(rowB + p * 16) * 128u + bc);

#pragma unroll
            for (int nf = 0; nf < 8; nf++) {
                uint32_t b0 = bf[nf >> 1][(nf & 1) * 2 + 0];
                uint32_t b1 = bf[nf >> 1][(nf & 1) * 2 + 1];
                mma16816(c[0][nf], af0, b0, b1);
                mma16816(c[1][nf], af1, b0, b1);
            }
        }

        sc = (sc == 2) ? 0 : sc + 1;
        sp = (sp == 2) ? 0 : sp + 1;
    }

    const int g  = lane >> 2;
    const int t4 = lane & 3;
#pragma unroll
    for (int mf = 0; mf < 2; mf++) {
#pragma unroll
        for (int nf = 0; nf < 8; nf++) {
            int row = bm + wm * 32 + mf * 16 + g;
            int col = bn + wn * 64 + nf * 8 + t4 * 2;
            *(float2*)(Cz + (size_t)row * N + col)       = make_float2(c[mf][nf][0], c[mf][nf][1]);
            *(float2*)(Cz + (size_t)(row + 8) * N + col) = make_float2(c[mf][nf][2], c[mf][nf][3]);
        }
    }
}

// ---------------- combine split-K partials ----------------
__global__ __launch_bounds__(256) void combine_kernel(const float* __restrict__ c01, float* __restrict__ out)
{
    int i = blockIdx.x * 256 + threadIdx.x;   // T_LEN*HID
    out[i] = c01[i] + c01[i + (size_t)T_LEN * HID];
}

// ---------------- bf16 hi/lo split ----------------
__device__ __forceinline__ void bf16split(float x, __nv_bfloat16& hi, __nv_bfloat16& lo) {
    hi = __float2bfloat16_rn(x);
    lo = __float2bfloat16_rn(x - __bfloat162float(hi));
}

// ---------------- split hs -> A3 bf16 [hi | lo | hi] ----------------
__global__ __launch_bounds__(256) void split_hs(const float* __restrict__ hs, __nv_bfloat16* __restrict__ A3)
{
    int idx = blockIdx.x * 256 + threadIdx.x;  // T*HID
    int t = idx >> 11, k = idx & 2047;
    __nv_bfloat16 hi, lo;
    bf16split(hs[idx], hi, lo);
    __nv_bfloat16* row = A3 + (size_t)t * K3;
    row[k] = hi; row[HID + k] = lo; row[2 * HID + k] = hi;
}

// ---------------- transpose+split proj weights -> B3 bf16 [PROJN_PAD][K3] = [hi | hi | lo] ----------------
__global__ __launch_bounds__(256) void tsplit_proj(
    const float* __restrict__ Wq, const float* __restrict__ Wk,
    const float* __restrict__ Wv, const float* __restrict__ Wg,
    const float* __restrict__ Wb, const float* __restrict__ Wa,
    __nv_bfloat16* __restrict__ B3)
{
    __shared__ float tile[32][33];
    int k0 = blockIdx.x * 32, n0 = blockIdx.y * 32;
    int tx = threadIdx.x & 31, ty = threadIdx.x >> 5;
#pragma unroll
    for (int i = 0; i < 4; i++) {
        int k = k0 + ty + i * 8, n = n0 + tx;
        float v;
        if      (n < KDIM)            v = Wq[(size_t)k * KDIM + n];
        else if (n < 2 * KDIM)        v = Wk[(size_t)k * KDIM + n - KDIM];
        else if (n < 2 * KDIM + VDIM) v = Wv[(size_t)k * VDIM + n - 2 * KDIM];
        else if (n < PROJN)           v = Wg[(size_t)k * VDIM + n - 2 * KDIM - VDIM];
        else if (n < PROJN + NH)      v = Wb[(size_t)k * NH + n - PROJN];
        else if (n < PROJN + 2 * NH)  v = Wa[(size_t)k * NH + n - PROJN - NH];
        else                          v = 0.f;
        tile[ty + i * 8][tx] = v;
    }
    __syncthreads();
#pragma unroll
    for (int i = 0; i < 4; i++) {
        int n = n0 + ty + i * 8, k = k0 + tx;
        __nv_bfloat16 hi, lo;
        bf16split(tile[tx][ty + i * 8], hi, lo);
        __nv_bfloat16* row = B3 + (size_t)n * K3;
        row[k] = hi; row[HID + k] = hi; row[2 * HID + k] = lo;
    }
}

// ---------------- transpose+split Wo -> B2 bf16 [HID][K3O] = [hi | hi | lo] ----------------
__global__ __launch_bounds__(256) void tsplit_wo(const float* __restrict__ Wo, __nv_bfloat16* __restrict__ B2)
{
    __shared__ float tile[32][33];
    int k0 = blockIdx.x * 32, n0 = blockIdx.y * 32;
    int tx = threadIdx.x & 31, ty = threadIdx.x >> 5;
#pragma unroll
    for (int i = 0; i < 4; i++) {
        int k = k0 + ty + i * 8, n = n0 + tx;
        tile[ty + i * 8][tx] = Wo[(size_t)k * HID + n];
    }
    __syncthreads();
#pragma unroll
    for (int i = 0; i < 4; i++) {
        int n = n0 + ty + i * 8, k = k0 + tx;
        __nv_bfloat16 hi, lo;
        bf16split(tile[tx][ty + i * 8], hi, lo);
        __nv_bfloat16* row = B2 + (size_t)n * K3O;
        row[k] = hi; row[VDIM + k] = hi; row[2 * VDIM + k] = lo;
    }
}

// ---------------- beta / g activations (g stored pre-exponentiated) ----------------
__global__ __launch_bounds__(256) void beta_g_finish(
    const float* __restrict__ proj,
    const float* __restrict__ A_log, const float* __restrict__ dt_bias,
    float* __restrict__ beta, float* __restrict__ egout)
{
    int idx = blockIdx.x * 256 + threadIdx.x;   // T*24
    if (idx >= T_LEN * 24) return;
    int t = idx / 24, c = idx % 24;
    float sv = proj[(size_t)t * PROJN_PAD + PROJN + c];
    if (c < NH) {
        beta[t * NH + c] = 1.f / (1.f + expf(-sv));
    } else {
        int hh = c - NH;
        float x = sv + dt_bias[hh];
        float sp = (x > 20.f) ? x : log1pf(expf(x));
        egout[t * NH + hh] = expf(-expf(A_log[hh]) * sp);   // exp(g)
    }
}

// ---------------- conv (K=4) + SiLU + per-head L2 norm for q,k ----------------
__global__ __launch_bounds__(128) void conv_norm_qk(
    const float* __restrict__ proj,
    const float* __restrict__ wq, const float* __restrict__ wk,
    float* __restrict__ qo, float* __restrict__ ko)
{
    int t = blockIdx.x, h = blockIdx.y, which = blockIdx.z;
    int colbase = which ? KDIM : 0;
    const float* w = which ? wk : wq;
    float* dst = which ? ko : qo;

    int c = h * DK + threadIdx.x;
    float y = 0.f;
#pragma unroll
    for (int i = 0; i < 4; i++) {
        int tt = t - 3 + i;
        if (tt >= 0) y = fmaf(proj[(size_t)tt * PROJN_PAD + colbase + c], w[c * 4 + i], y);
    }
    y = y / (1.f + expf(-y));

    float ss = y * y;
#pragma unroll
    for (int off = 16; off; off >>= 1)
        ss += __shfl_xor_sync(0xffffffffu, ss, off);
    __shared__ float red[4];
    int lane = threadIdx.x & 31, warp = threadIdx.x >> 5;
    if (lane == 0) red[warp] = ss;
    __syncthreads();
    float tot = red[0] + red[1] + red[2] + red[3];
    dst[(size_t)t * KDIM + c] = y * rsqrtf(tot + 1e-6f);
}

// ---------------- conv (K=4) + SiLU for v ----------------
__global__ __launch_bounds__(256) void conv_v_kernel(
    const float* __restrict__ proj, const float* __restrict__ wv, float* __restrict__ vo)
{
    int idx = blockIdx.x * 256 + threadIdx.x;   // T*VDIM
    int c = idx % VDIM, t = idx / VDIM;
    float y = 0.f;
#pragma unroll
    for (int i = 0; i < 4; i++) {
        int tt = t - 3 + i;
        if (tt >= 0) y = fmaf(proj[(size_t)tt * PROJN_PAD + 2 * KDIM + c], wv[c * 4 + i], y);
    }
    vo[idx] = y / (1.f + expf(-y));
}

// ---------------- gated delta-rule scan: 96 CTAs, 2 barriers/step ----------------
// o_t = e^g (q.S_old) + (q.k) delta ; delta_j = (v_j - e^g (k.S_old)_j) beta
__global__ __launch_bounds__(256) void scan_kernel(
    const float* __restrict__ q, const float* __restrict__ k,
    const float* __restrict__ v, const float* __restrict__ eg_in,
    const float* __restrict__ bb, float* __restrict__ o)
{
    int h = blockIdx.x >> 3;
    int chunk = blockIdx.x & 7;
    int tid = threadIdx.x;
    int j = tid & 31;          // column (== lane)
    int kg = tid >> 5;         // warp = k-row group of 16

    __shared__ float ksh[2][128], qsh[2][128], vsh[2][32];
    __shared__ float pdk[8][32], pdq[8][32], pqk[8];
    __shared__ float gb[2][2];

    float S[16];
#pragma unroll
    for (int i = 0; i < 16; i++) S[i] = 0.f;

    const int kq_base = h * DK;
    const int v_base = h * DV + chunk * 32;

    // prefetch t=0
    float pk, pv = 0.f, pgb = 0.f;
    if (tid < 128) pk = k[kq_base + tid];
    else           pk = q[kq_base + tid - 128];
    if (tid < 32)  pv = v[v_base + tid];
    if (tid == 32) pgb = eg_in[h];
    if (tid == 33) pgb = bb[h];

    for (int t = 0; t < T_LEN; t++) {
        int b = t & 1;
        // stage prefetched values into buffer b (no race: buffer b last read at t-2,
        // separated by barrier A of t-1 and t)
        if (tid < 128) ksh[b][tid] = pk;
        else           qsh[b][tid - 128] = pk;
        if (tid < 32)  vsh[b][tid] = pv;
        if (tid == 32) gb[b][0] = pgb;
        if (tid == 33) gb[b][1] = pgb;
        __syncthreads();                                    // (A)

        // prefetch t+1 (overlaps compute)
        if (t + 1 < T_LEN) {
            size_t r = (size_t)(t + 1);
            if (tid < 128) pk = k[r * KDIM + kq_base + tid];
            else           pk = q[r * KDIM + kq_base + tid - 128];
            if (tid < 32)  pv = v[r * VDIM + v_base + tid];
            if (tid == 32) pgb = eg_in[r * NH + h];
            if (tid == 33) pgb = bb[r * NH + h];
        }

        float eg = gb[b][0];
        float bet = gb[b][1];
        const float* kk = &ksh[b][kg * 16];
        const float* qq = &qsh[b][kg * 16];

        // dual partial reductions over my 16 rows
        float pk_ = 0.f, pq_ = 0.f;
#pragma unroll
        for (int i = 0; i < 16; i++) {
            pk_ = fmaf(kk[i], S[i], pk_);
            pq_ = fmaf(qq[i], S[i], pq_);
        }
        pdk[kg][j] = pk_;
        pdq[kg][j] = pq_;

        // per-warp q.k partial (lanes 0..15 cover the warp's 16 rows)
        float qkp = (j < 16) ? qq[j] * kk[j] : 0.f;
#pragma unroll
        for (int off = 16; off; off >>= 1)
            qkp += __shfl_xor_sync(0xffffffffu, qkp, off);
        if (j == 0) pqk[kg] = qkp;
        __syncthreads();                                    // (B)

        float kS = 0.f, qS = 0.f, qk = 0.f;
#pragma unroll
        for (int g2 = 0; g2 < 8; g2++) {
            kS += pdk[g2][j];
            qS += pdq[g2][j];
            qk += pqk[g2];
        }
        float d = (vsh[b][j] - eg * kS) * bet;
        if (kg == 0)
            o[(size_t)t * VDIM + v_base + j] = fmaf(eg, qS, qk * d);

#pragma unroll
        for (int i = 0; i < 16; i++)
            S[i] = fmaf(S[i], eg, kk[i] * d);
    }
}

// ---------------- RMSNorm * norm_w * SiLU(gate), fused bf16 split -> A2 [hi | lo | hi] ----------------
__global__ __launch_bounds__(256) void epilogue_kernel(
    const float* __restrict__ o, const float* __restrict__ proj,
    const float* __restrict__ norm_w, __nv_bfloat16* __restrict__ A2)
{
    int t = blockIdx.x, h = blockIdx.y;
    int d = threadIdx.x;
    float x = o[(size_t)t * VDIM + h * DV + d];

    float ss = x * x;
#pragma unroll
    for (int off = 16; off; off >>= 1)
        ss += __shfl_xor_sync(0xffffffffu, ss, off);
    __shared__ float red[8];
    int lane = threadIdx.x & 31, warp = threadIdx.x >> 5;
    if (lane == 0) red[warp] = ss;
    __syncthreads();
    float tot = 0.f;
#pragma unroll
    for (int w = 0; w < 8; w++) tot += red[w];

    float scale = rsqrtf(tot * (1.f / 256.f) + 1e-5f);
    float g = proj[(size_t)t * PROJN_PAD + 2 * KDIM + VDIM + h * DV + d];
    float silu_g = g / (1.f + expf(-g));
    float val = x * scale * norm_w[d] * silu_g;

    __nv_bfloat16 hi, lo;
    bf16split(val, hi, lo);
    __nv_bfloat16* row = A2 + (size_t)t * K3O;
    int col = h * DV + d;
    row[col] = hi; row[VDIM + col] = lo; row[2 * VDIM + col] = hi;
}

// ---------------- launch ----------------
extern "C" void kernel_launch(void* const* d_in, const int* in_sizes, int n_in,
                              void* d_out, int out_size)
{
    const float* hs      = (const float*)d_in[0];
    const float* Wq      = (const float*)d_in[1];
    const float* Wk      = (const float*)d_in[2];
    const float* Wv      = (const float*)d_in[3];
    const float* Wb      = (const float*)d_in[4];
    const float* Wa      = (const float*)d_in[5];
    const float* Wg      = (const float*)d_in[6];
    const float* Wo      = (const float*)d_in[7];
    const float* conv_wq = (const float*)d_in[8];
    const float* conv_wk = (const float*)d_in[9];
    const float* conv_wv = (const float*)d_in[10];
    const float* A_log   = (const float*)d_in[11];
    const float* dt_bias = (const float*)d_in[12];
    const float* norm_w  = (const float*)d_in[13];
    float* out = (float*)d_out;

    unsigned char* s = nullptr;
    cudaGetSymbolAddress((void**)&s, g_scratch);
    float*          PROJ  = (float*)(s + B_PROJ);
    __nv_bfloat16*  A3    = (__nv_bfloat16*)(s + B_A3);
    __nv_bfloat16*  B3    = (__nv_bfloat16*)(s + B_B3);
    __nv_bfloat16*  A2    = (__nv_bfloat16*)(s + B_A2);
    __nv_bfloat16*  B2    = (__nv_bfloat16*)(s + B_B2);
    float*          Qb    = (float*)(s + B_Q);
    float*          Kb    = (float*)(s + B_K);
    float*          Vb    = (float*)(s + B_V);
    float*          Ob    = (float*)(s + B_O);
    float*          Gb    = (float*)(s + B_G);
    float*          Bb    = (float*)(s + B_BB);
    float*          Cpart = (float*)(s + B_B3);   // reuse B3 region after proj GEMM

    cudaFuncSetAttribute(gemm_bf16, cudaFuncAttributeMaxDynamicSharedMemorySize, GEMM_SMEM);

    // 1) bf16 hi/lo splits (beta/a weights folded into B3 padding columns)
    split_hs<<<(T_LEN * HID) / 256, 256>>>(hs, A3);
    tsplit_proj<<<dim3(HID / 32, PROJN_PAD / 32), 256>>>(Wq, Wk, Wv, Wg, Wb, Wa, B3);
    tsplit_wo<<<dim3(VDIM / 32, HID / 32), 256>>>(Wo, B2);

    // 2) fused projection GEMM: PROJ[1024,9344] = A3 @ B3^T
    gemm_bf16<<<dim3(T_LEN / 128, PROJN_PAD / 128, 1), 256, GEMM_SMEM>>>(A3, B3, PROJ, T_LEN, PROJN_PAD, K3, K3);

    // 3) beta / exp(g) activations
    beta_g_finish<<<(T_LEN * 24 + 255) / 256, 256>>>(PROJ, A_log, dt_bias, Bb, Gb);
    // 4) conv + silu (+ l2norm for q,k)
    conv_norm_qk<<<dim3(T_LEN, NH, 2), 128>>>(PROJ, conv_wq, conv_wk, Qb, Kb);
    conv_v_kernel<<<(T_LEN * VDIM) / 256, 256>>>(PROJ, conv_wv, Vb);
    // 5) sequential gated delta scan
    scan_kernel<<<NH * 8, 256>>>(Qb, Kb, Vb, Gb, Bb, Ob);
    // 6) rmsnorm * swish-gate, fused split into A2
    epilogue_kernel<<<dim3(T_LEN, NH), 256>>>(Ob, PROJ, norm_w, A2);
    // 7) output GEMM, split-K=2 into Cpart, then combine
    gemm_bf16<<<dim3(T_LEN / 128, HID / 128, 2), 256, GEMM_SMEM>>>(A2, B2, Cpart, T_LEN, HID, K3O, K3O / 2);
    combine_kernel<<<(T_LEN * HID) / 256, 256>>>(Cpart, out);
}

// round 8
// speedup vs baseline: 2.5550x; 1.2671x over previous
#include <cuda_runtime.h>
#include <cuda_bf16.h>
#include <math.h>
#include <stdint.h>

// ---------------- problem constants ----------------
#define T_LEN 1024
#define HID   2048
#define NH    12
#define DK    128
#define DV    256
#define KDIM  1536
#define VDIM  3072
#define PROJN 9216
#define PROJN_PAD 9344
#define K3    6144
#define K3O   9216

// ---------------- scratch ----------------
constexpr size_t SZ_PROJ = (size_t)T_LEN * PROJN_PAD * 4;
constexpr size_t SZ_A3   = (size_t)T_LEN * K3 * 2;
constexpr size_t SZ_B3   = (size_t)PROJN_PAD * K3 * 2;
constexpr size_t SZ_A2   = (size_t)T_LEN * K3O * 2;
constexpr size_t SZ_B2   = (size_t)HID * K3O * 2;
constexpr size_t SZ_QK   = (size_t)T_LEN * KDIM * 4;
constexpr size_t SZ_V    = (size_t)T_LEN * VDIM * 4;
constexpr size_t SZ_H    = (size_t)T_LEN * NH * 4;

constexpr size_t B_PROJ = 0;
constexpr size_t B_A3   = B_PROJ + SZ_PROJ;
constexpr size_t B_B3   = B_A3 + SZ_A3;
constexpr size_t B_A2   = B_B3 + SZ_B3;
constexpr size_t B_B2   = B_A2 + SZ_A2;
constexpr size_t B_Q    = B_B2 + SZ_B2;
constexpr size_t B_K    = B_Q + SZ_QK;
constexpr size_t B_V    = B_K + SZ_QK;
constexpr size_t B_O    = B_V + SZ_V;
constexpr size_t B_G    = B_O + SZ_V;
constexpr size_t B_BB   = B_G + SZ_H;
constexpr size_t SCRATCH_BYTES = B_BB + SZ_H;

__device__ __align__(256) unsigned char g_scratch[SCRATCH_BYTES];

// ---------------- PTX helpers ----------------
__device__ __forceinline__ uint32_t smem_u32(const void* p) {
    uint32_t a;
    asm("{ .reg .u64 t; cvta.to.shared.u64 t, %1; cvt.u32.u64 %0, t; }" : "=r"(a) : "l"(p));
    return a;
}
__device__ __forceinline__ void cpasync16(uint32_t dst, const void* src) {
    asm volatile("cp.async.cg.shared.global [%0], [%1], 16;" :: "r"(dst), "l"(src) : "memory");
}
#define CP_COMMIT() asm volatile("cp.async.commit_group;" ::: "memory")
#define CP_WAIT0()  asm volatile("cp.async.wait_group 0;" ::: "memory")
#define CP_WAIT1()  asm volatile("cp.async.wait_group 1;" ::: "memory")

__device__ __forceinline__ void ldm4(uint32_t* r, uint32_t addr) {
    asm volatile("ldmatrix.sync.aligned.m8n8.x4.shared.b16 {%0,%1,%2,%3}, [%4];"
        : "=r"(r[0]), "=r"(r[1]), "=r"(r[2]), "=r"(r[3]) : "r"(addr));
}
__device__ __forceinline__ void mma16816(float* c, const uint32_t* a, uint32_t b0, uint32_t b1) {
    asm volatile("mma.sync.aligned.m16n8k16.row.col.f32.bf16.bf16.f32 "
        "{%0,%1,%2,%3}, {%4,%5,%6,%7}, {%8,%9}, {%0,%1,%2,%3};"
        : "+f"(c[0]), "+f"(c[1]), "+f"(c[2]), "+f"(c[3])
        : "r"(a[0]), "r"(a[1]), "r"(a[2]), "r"(a[3]), "r"(b0), "r"(b1));
}
#define SWZ128(o) ((o) ^ (((o) >> 3) & 0x70))

// ---------------- bf16 mma.sync GEMM (unchanged from R7) ----------------
#define GEMM_SMEM 98304

__global__ __launch_bounds__(256, 2) void gemm_bf16(
    const __nv_bfloat16* __restrict__ A, const __nv_bfloat16* __restrict__ Bt,
    float* __restrict__ C, int M, int N, int K, int kCount)
{
    extern __shared__ unsigned char smem_raw[];
    uint32_t sb = smem_u32(smem_raw);

    const int tid  = threadIdx.x;
    const int wid  = tid >> 5;
    const int lane = tid & 31;
    const int wm   = wid & 3;
    const int wn   = wid >> 2;

    const int bm = blockIdx.x * 128;
    const int bn = blockIdx.y * 128;
    const int kStart = blockIdx.z * kCount;
    float* Cz = C + (size_t)blockIdx.z * M * N;

    const int lrow = tid >> 1;
    const int lcol = (tid & 1) * 64;
    const unsigned char* Ag = (const unsigned char*)(A + (size_t)(bm + lrow) * K + kStart) + lcol;
    const unsigned char* Bg = (const unsigned char*)(Bt + (size_t)(bn + lrow) * K + kStart) + lcol;
    uint32_t st[4];
#pragma unroll
    for (int j = 0; j < 4; j++) {
        uint32_t o = (uint32_t)lrow * 128u + (uint32_t)lcol + j * 16u;
        st[j] = SWZ128(o);
    }

    const int l8 = lane & 7;
    const int rowA = wm * 32 + ((lane >> 3) & 1) * 8 + l8;
    const uint32_t colA = (uint32_t)((lane >> 4) * 16);
    const uint32_t xorA = (uint32_t)((rowA & 7) << 4);
    const int rowB = wn * 64 + ((lane >> 4) & 1) * 8 + l8;
    const uint32_t colB = (uint32_t)(((lane >> 3) & 1) * 16);
    const uint32_t xorB = (uint32_t)((rowB & 7) << 4);

    float c[2][8][4];
#pragma unroll
    for (int mf = 0; mf < 2; mf++)
#pragma unroll
        for (int nf = 0; nf < 8; nf++)
#pragma unroll
            for (int i = 0; i < 4; i++) c[mf][nf][i] = 0.f;

    const int chunks = kCount >> 6;

#pragma unroll
    for (int p = 0; p < 2; p++) {
        uint32_t ab = sb + (uint32_t)p * 32768u;
        uint32_t bb = ab + 16384u;
#pragma unroll
        for (int j = 0; j < 4; j++) cpasync16(ab + st[j], Ag + j * 16);
#pragma unroll
        for (int j = 0; j < 4; j++) cpasync16(bb + st[j], Bg + j * 16);
        Ag += 128; Bg += 128;
        CP_COMMIT();
    }

    int sc = 0;
    int sp = 2;

    for (int i = 0; i < chunks; i++) {
        CP_WAIT1();
        __syncthreads();

        if (i + 2 < chunks) {
            uint32_t ab2 = sb + (uint32_t)sp * 32768u;
            uint32_t bb2 = ab2 + 16384u;
#pragma unroll
            for (int j = 0; j < 4; j++) cpasync16(ab2 + st[j], Ag + j * 16);
#pragma unroll
            for (int j = 0; j < 4; j++) cpasync16(bb2 + st[j], Bg + j * 16);
            Ag += 128; Bg += 128;
        }
        CP_COMMIT();

        uint32_t ab = sb + (uint32_t)sc * 32768u;
        uint32_t bb = ab + 16384u;
#pragma unroll
        for (int ks = 0; ks < 4; ks++) {
            uint32_t af0[4], af1[4];
            uint32_t ac = ((uint32_t)(ks * 32) + colA) ^ xorA;
            ldm4(af0, ab + (uint32_t)rowA * 128u + ac);
            ldm4(af1, ab + (uint32_t)rowA * 128u + 2048u + ac);

            uint32_t bf[4][4];
            uint32_t bc = ((uint32_t)(ks * 32) + colB) ^ xorB;
#pragma unroll
            for (int p = 0; p < 4; p++)
                ldm4(bf[p], bb + (uint32_t)(rowB + p * 16) * 128u + bc);

#pragma unroll
            for (int nf = 0; nf < 8; nf++) {
                uint32_t b0 = bf[nf >> 1][(nf & 1) * 2 + 0];
                uint32_t b1 = bf[nf >> 1][(nf & 1) * 2 + 1];
                mma16816(c[0][nf], af0, b0, b1);
                mma16816(c[1][nf], af1, b0, b1);
            }
        }

        sc = (sc == 2) ? 0 : sc + 1;
        sp = (sp == 2) ? 0 : sp + 1;
    }

    const int g  = lane >> 2;
    const int t4 = lane & 3;
#pragma unroll
    for (int mf = 0; mf < 2; mf++) {
#pragma unroll
        for (int nf = 0; nf < 8; nf++) {
            int row = bm + wm * 32 + mf * 16 + g;
            int col = bn + wn * 64 + nf * 8 + t4 * 2;
            *(float2*)(Cz + (size_t)row * N + col)       = make_float2(c[mf][nf][0], c[mf][nf][1]);
            *(float2*)(Cz + (size_t)(row + 8) * N + col) = make_float2(c[mf][nf][2], c[mf][nf][3]);
        }
    }
}

__global__ __launch_bounds__(256) void combine_kernel(const float* __restrict__ c01, float* __restrict__ out)
{
    int i = blockIdx.x * 256 + threadIdx.x;
    out[i] = c01[i] + c01[i + (size_t)T_LEN * HID];
}

// ---------------- bf16 hi/lo split ----------------
__device__ __forceinline__ void bf16split(float x, __nv_bfloat16& hi, __nv_bfloat16& lo) {
    hi = __float2bfloat16_rn(x);
    lo = __float2bfloat16_rn(x - __bfloat162float(hi));
}

__global__ __launch_bounds__(256) void split_hs(const float* __restrict__ hs, __nv_bfloat16* __restrict__ A3)
{
    int idx = blockIdx.x * 256 + threadIdx.x;
    int t = idx >> 11, k = idx & 2047;
    __nv_bfloat16 hi, lo;
    bf16split(hs[idx], hi, lo);
    __nv_bfloat16* row = A3 + (size_t)t * K3;
    row[k] = hi; row[HID + k] = lo; row[2 * HID + k] = hi;
}

__global__ __launch_bounds__(256) void tsplit_proj(
    const float* __restrict__ Wq, const float* __restrict__ Wk,
    const float* __restrict__ Wv, const float* __restrict__ Wg,
    const float* __restrict__ Wb, const float* __restrict__ Wa,
    __nv_bfloat16* __restrict__ B3)
{
    __shared__ float tile[32][33];
    int k0 = blockIdx.x * 32, n0 = blockIdx.y * 32;
    int tx = threadIdx.x & 31, ty = threadIdx.x >> 5;
#pragma unroll
    for (int i = 0; i < 4; i++) {
        int k = k0 + ty + i * 8, n = n0 + tx;
        float v;
        if      (n < KDIM)            v = Wq[(size_t)k * KDIM + n];
        else if (n < 2 * KDIM)        v = Wk[(size_t)k * KDIM + n - KDIM];
        else if (n < 2 * KDIM + VDIM) v = Wv[(size_t)k * VDIM + n - 2 * KDIM];
        else if (n < PROJN)           v = Wg[(size_t)k * VDIM + n - 2 * KDIM - VDIM];
        else if (n < PROJN + NH)      v = Wb[(size_t)k * NH + n - PROJN];
        else if (n < PROJN + 2 * NH)  v = Wa[(size_t)k * NH + n - PROJN - NH];
        else                          v = 0.f;
        tile[ty + i * 8][tx] = v;
    }
    __syncthreads();
#pragma unroll
    for (int i = 0; i < 4; i++) {
        int n = n0 + ty + i * 8, k = k0 + tx;
        __nv_bfloat16 hi, lo;
        bf16split(tile[tx][ty + i * 8], hi, lo);
        __nv_bfloat16* row = B3 + (size_t)n * K3;
        row[k] = hi; row[HID + k] = hi; row[2 * HID + k] = lo;
    }
}

__global__ __launch_bounds__(256) void tsplit_wo(const float* __restrict__ Wo, __nv_bfloat16* __restrict__ B2)
{
    __shared__ float tile[32][33];
    int k0 = blockIdx.x * 32, n0 = blockIdx.y * 32;
    int tx = threadIdx.x & 31, ty = threadIdx.x >> 5;
#pragma unroll
    for (int i = 0; i < 4; i++) {
        int k = k0 + ty + i * 8, n = n0 + tx;
        tile[ty + i * 8][tx] = Wo[(size_t)k * HID + n];
    }
    __syncthreads();
#pragma unroll
    for (int i = 0; i < 4; i++) {
        int n = n0 + ty + i * 8, k = k0 + tx;
        __nv_bfloat16 hi, lo;
        bf16split(tile[tx][ty + i * 8], hi, lo);
        __nv_bfloat16* row = B2 + (size_t)n * K3O;
        row[k] = hi; row[VDIM + k] = hi; row[2 * VDIM + k] = lo;
    }
}

__global__ __launch_bounds__(256) void beta_g_finish(
    const float* __restrict__ proj,
    const float* __restrict__ A_log, const float* __restrict__ dt_bias,
    float* __restrict__ beta, float* __restrict__ egout)
{
    int idx = blockIdx.x * 256 + threadIdx.x;
    if (idx >= T_LEN * 24) return;
    int t = idx / 24, c = idx % 24;
    float sv = proj[(size_t)t * PROJN_PAD + PROJN + c];
    if (c < NH) {
        beta[t * NH + c] = 1.f / (1.f + expf(-sv));
    } else {
        int hh = c - NH;
        float x = sv + dt_bias[hh];
        float sp = (x > 20.f) ? x : log1pf(expf(x));
        egout[t * NH + hh] = expf(-expf(A_log[hh]) * sp);   // exp(g)
    }
}

__global__ __launch_bounds__(128) void conv_norm_qk(
    const float* __restrict__ proj,
    const float* __restrict__ wq, const float* __restrict__ wk,
    float* __restrict__ qo, float* __restrict__ ko)
{
    int t = blockIdx.x, h = blockIdx.y, which = blockIdx.z;
    int colbase = which ? KDIM : 0;
    const float* w = which ? wk : wq;
    float* dst = which ? ko : qo;

    int c = h * DK + threadIdx.x;
    float y = 0.f;
#pragma unroll
    for (int i = 0; i < 4; i++) {
        int tt = t - 3 + i;
        if (tt >= 0) y = fmaf(proj[(size_t)tt * PROJN_PAD + colbase + c], w[c * 4 + i], y);
    }
    y = y / (1.f + expf(-y));

    float ss = y * y;
#pragma unroll
    for (int off = 16; off; off >>= 1)
        ss += __shfl_xor_sync(0xffffffffu, ss, off);
    __shared__ float red[4];
    int lane = threadIdx.x & 31, warp = threadIdx.x >> 5;
    if (lane == 0) red[warp] = ss;
    __syncthreads();
    float tot = red[0] + red[1] + red[2] + red[3];
    dst[(size_t)t * KDIM + c] = y * rsqrtf(tot + 1e-6f);
}

__global__ __launch_bounds__(256) void conv_v_kernel(
    const float* __restrict__ proj, const float* __restrict__ wv, float* __restrict__ vo)
{
    int idx = blockIdx.x * 256 + threadIdx.x;
    int c = idx % VDIM, t = idx / VDIM;
    float y = 0.f;
#pragma unroll
    for (int i = 0; i < 4; i++) {
        int tt = t - 3 + i;
        if (tt >= 0) y = fmaf(proj[(size_t)tt * PROJN_PAD + 2 * KDIM + c], wv[c * 4 + i], y);
    }
    vo[idx] = y / (1.f + expf(-y));
}

// ---------------- block-processed gated delta-rule scan (B=8 steps / barrier group) ----------------
// 96 CTAs = 12 heads x 8 column-chunks of 32. 256 threads: g=warp (16 k-rows), j=lane (column).
// Per block of 8 steps:  delta_i = beta_i (v_i - E_i (k_i.S0) - sum_{s<i} r_is (k_i.k_s) delta_s)
//                        o_i     = E_i (q_i.S0) + sum_{s<=i} r_is (q_i.k_s) delta_s
//                        S      <- E_7 S0 + sum_s k_s (r_7s delta_s)
#define NBLK 128

__global__ __launch_bounds__(256) void scan_block_kernel(
    const float* __restrict__ q, const float* __restrict__ k,
    const float* __restrict__ v, const float* __restrict__ eg_in,
    const float* __restrict__ bb, float* __restrict__ o)
{
    const int h = blockIdx.x >> 3;
    const int chunk = blockIdx.x & 7;
    const int tid = threadIdx.x;
    const int j = tid & 31;
    const int g = tid >> 5;
    const int G = g * 16;

    __shared__ float ksh[2][8][128];
    __shared__ float qsh[2][8][128];
    __shared__ float vsh[2][8][32];
    __shared__ float egb[2][2][8];       // [buf][0=eg 1=beta][i]
    __shared__ float pdk[8][32 * 9];     // [i][j*9+g]
    __shared__ float pdq[8][32 * 9];
    __shared__ float pscK[64][9];        // [pair][g]
    __shared__ float pscQ[64][9];
    __shared__ float scalK[64], scalQ[64];
    __shared__ float wsh[8][32];
    __shared__ float E7sh;

    float S[16];
#pragma unroll
    for (int i = 0; i < 16; i++) S[i] = 0.f;

    const int kq_base = h * DK;
    const int v_base  = h * DV + chunk * 32;

    // cp.async source/dest mapping
    const int ki  = tid >> 5;                 // 0..7 row(step)
    const int kf  = (tid & 31) * 4;           // float offset in row
    const int vi  = tid >> 3;                 // for v (tid<64)
    const int vf  = (tid & 7) * 4;
    uint32_t kdst[2], qdst[2], vdst[2];
#pragma unroll
    for (int p = 0; p < 2; p++) {
        kdst[p] = smem_u32(&ksh[p][ki][kf]);
        qdst[p] = smem_u32(&qsh[p][ki][kf]);
        vdst[p] = smem_u32(&vsh[p][0][0]) + (uint32_t)(vi * 32 + vf) * 4u;
    }

    // eg/beta register prefetch lanes: tid 192..207
    const int eb_i   = tid - 192;            // 0..15 ; <8 => eg, >=8 => beta
    float pebs = 0.f;
    if (eb_i >= 0 && eb_i < 16) {
        int i0 = eb_i & 7;
        pebs = (eb_i < 8) ? eg_in[(size_t)i0 * NH + h] : bb[(size_t)i0 * NH + h];
    }

    // prologue: cp.async block 0 into buf 0
    {
        const float* kp = k + (size_t)ki * KDIM + kq_base + kf;
        const float* qp = q + (size_t)ki * KDIM + kq_base + kf;
        cpasync16(kdst[0], kp);
        cpasync16(qdst[0], qp);
        if (tid < 64) cpasync16(vdst[0], v + (size_t)vi * VDIM + v_base + vf);
        CP_COMMIT();
    }

    for (int b = 0; b < NBLK; b++) {
        const int buf = b & 1;
        const int t0 = b * 8;

        CP_WAIT0();
        if (eb_i >= 0 && eb_i < 16)
            egb[buf][eb_i >> 3][eb_i & 7] = pebs;
        __syncthreads();                                  // block data ready

        // issue next block's loads (overlap with compute)
        if (b + 1 < NBLK) {
            const int nb = (b + 1) & 1;
            const size_t r0 = (size_t)(t0 + 8);
            cpasync16(kdst[nb], k + (r0 + ki) * KDIM + kq_base + kf);
            cpasync16(qdst[nb], q + (r0 + ki) * KDIM + kq_base + kf);
            if (tid < 64) cpasync16(vdst[nb], v + (r0 + vi) * VDIM + v_base + vf);
            if (eb_i >= 0 && eb_i < 16) {
                int i0 = eb_i & 7;
                pebs = (eb_i < 8) ? eg_in[(r0 + i0) * NH + h] : bb[(r0 + i0) * NH + h];
            }
            CP_COMMIT();
        }

        // ---- P1: vector partials k_i.S0, q_i.S0 over my 16 rows ----
#pragma unroll
        for (int i = 0; i < 8; i++) {
            float pk = 0.f, pq = 0.f;
#pragma unroll
            for (int r4 = 0; r4 < 4; r4++) {
                float4 kv = *(const float4*)&ksh[buf][i][G + r4 * 4];
                float4 qv = *(const float4*)&qsh[buf][i][G + r4 * 4];
                pk = fmaf(kv.x, S[r4*4+0], pk); pk = fmaf(kv.y, S[r4*4+1], pk);
                pk = fmaf(kv.z, S[r4*4+2], pk); pk = fmaf(kv.w, S[r4*4+3], pk);
                pq = fmaf(qv.x, S[r4*4+0], pq); pq = fmaf(qv.y, S[r4*4+1], pq);
                pq = fmaf(qv.z, S[r4*4+2], pq); pq = fmaf(qv.w, S[r4*4+3], pq);
            }
            pdk[i][j * 9 + g] = pk;
            pdq[i][j * 9 + g] = pq;
        }

        // ---- P1b: scalar partials K_is = k_i.k_s, Q_is = q_i.k_s (pairs p = j, j+32) ----
#pragma unroll
        for (int m = 0; m < 2; m++) {
            int p = j + m * 32;
            int si = p >> 3, ss = p & 7;
            float sk = 0.f, sq = 0.f;
#pragma unroll
            for (int r4 = 0; r4 < 4; r4++) {
                float4 a = *(const float4*)&ksh[buf][si][G + r4 * 4];
                float4 qa = *(const float4*)&qsh[buf][si][G + r4 * 4];
                float4 c = *(const float4*)&ksh[buf][ss][G + r4 * 4];
                sk = fmaf(a.x, c.x, sk); sk = fmaf(a.y, c.y, sk);
                sk = fmaf(a.z, c.z, sk); sk = fmaf(a.w, c.w, sk);
                sq = fmaf(qa.x, c.x, sq); sq = fmaf(qa.y, c.y, sq);
                sq = fmaf(qa.z, c.z, sq); sq = fmaf(qa.w, c.w, sq);
            }
            pscK[p][g] = sk;
            pscQ[p][g] = sq;
        }
        __syncthreads();                                  // partials ready

        // ---- P3: solver warp ----
        if (g == 0) {
            // reduce scalars
#pragma unroll
            for (int m = 0; m < 2; m++) {
                int p = j + m * 32;
                float sk = 0.f, sq = 0.f;
#pragma unroll
                for (int gg = 0; gg < 8; gg++) { sk += pscK[p][gg]; sq += pscQ[p][gg]; }
                scalK[p] = sk; scalQ[p] = sq;
            }
            // reduce vectors (my column j)
            float a[8], bq[8];
#pragma unroll
            for (int i = 0; i < 8; i++) {
                float sa = 0.f, sb = 0.f;
#pragma unroll
                for (int gg = 0; gg < 8; gg++) {
                    sa += pdk[i][j * 9 + gg];
                    sb += pdq[i][j * 9 + gg];
                }
                a[i] = sa; bq[i] = sb;
            }
            __syncwarp();

            float eg[8], bet[8], E[8];
            float Ec = 1.f;
#pragma unroll
            for (int i = 0; i < 8; i++) {
                eg[i]  = egb[buf][0][i];
                bet[i] = egb[buf][1][i];
                Ec *= eg[i];
                E[i] = Ec;
            }

            float dlt[8];
#pragma unroll
            for (int i = 0; i < 8; i++) {
                float acc = vsh[buf][i][j] - E[i] * a[i];
                float rr = 1.f;
#pragma unroll
                for (int s = i - 1; s >= 0; s--) {
                    rr *= eg[s + 1];
                    acc -= rr * scalK[i * 8 + s] * dlt[s];
                }
                dlt[i] = bet[i] * acc;
                float oacc = fmaf(E[i], bq[i], scalQ[i * 8 + i] * dlt[i]);
                rr = 1.f;
#pragma unroll
                for (int s = i - 1; s >= 0; s--) {
                    rr *= eg[s + 1];
                    oacc = fmaf(rr * scalQ[i * 8 + s], dlt[s], oacc);
                }
                o[(size_t)(t0 + i) * VDIM + v_base + j] = oacc;
            }
            // state-update coefficients w_s = r_{7,s} * delta_s
            float rr = 1.f;
#pragma unroll
            for (int s = 7; s >= 0; s--) {
                wsh[s][j] = rr * dlt[s];
                rr *= eg[s];
            }
            if (j == 0) E7sh = E[7];
        }
        __syncthreads();                                  // deltas ready

        // ---- P5: rank-8 state update ----
        float E7 = E7sh;
        float w[8];
#pragma unroll
        for (int s = 0; s < 8; s++) w[s] = wsh[s][j];
#pragma unroll
        for (int r = 0; r < 16; r++) S[r] *= E7;
#pragma unroll
        for (int s = 0; s < 8; s++) {
#pragma unroll
            for (int r4 = 0; r4 < 4; r4++) {
                float4 kv = *(const float4*)&ksh[buf][s][G + r4 * 4];
                S[r4*4+0] = fmaf(kv.x, w[s], S[r4*4+0]);
                S[r4*4+1] = fmaf(kv.y, w[s], S[r4*4+1]);
                S[r4*4+2] = fmaf(kv.z, w[s], S[r4*4+2]);
                S[r4*4+3] = fmaf(kv.w, w[s], S[r4*4+3]);
            }
        }
    }
}

// ---------------- RMSNorm * norm_w * SiLU(gate), fused bf16 split -> A2 ----------------
__global__ __launch_bounds__(256) void epilogue_kernel(
    const float* __restrict__ o, const float* __restrict__ proj,
    const float* __restrict__ norm_w, __nv_bfloat16* __restrict__ A2)
{
    int t = blockIdx.x, h = blockIdx.y;
    int d = threadIdx.x;
    float x = o[(size_t)t * VDIM + h * DV + d];

    float ss = x * x;
#pragma unroll
    for (int off = 16; off; off >>= 1)
        ss += __shfl_xor_sync(0xffffffffu, ss, off);
    __shared__ float red[8];
    int lane = threadIdx.x & 31, warp = threadIdx.x >> 5;
    if (lane == 0) red[warp] = ss;
    __syncthreads();
    float tot = 0.f;
#pragma unroll
    for (int w = 0; w < 8; w++) tot += red[w];

    float scale = rsqrtf(tot * (1.f / 256.f) + 1e-5f);
    float gg = proj[(size_t)t * PROJN_PAD + 2 * KDIM + VDIM + h * DV + d];
    float silu_g = gg / (1.f + expf(-gg));
    float val = x * scale * norm_w[d] * silu_g;

    __nv_bfloat16 hi, lo;
    bf16split(val, hi, lo);
    __nv_bfloat16* row = A2 + (size_t)t * K3O;
    int col = h * DV + d;
    row[col] = hi; row[VDIM + col] = lo; row[2 * VDIM + col] = hi;
}

// ---------------- launch ----------------
extern "C" void kernel_launch(void* const* d_in, const int* in_sizes, int n_in,
                              void* d_out, int out_size)
{
    const float* hs      = (const float*)d_in[0];
    const float* Wq      = (const float*)d_in[1];
    const float* Wk      = (const float*)d_in[2];
    const float* Wv      = (const float*)d_in[3];
    const float* Wb      = (const float*)d_in[4];
    const float* Wa      = (const float*)d_in[5];
    const float* Wg      = (const float*)d_in[6];
    const float* Wo      = (const float*)d_in[7];
    const float* conv_wq = (const float*)d_in[8];
    const float* conv_wk = (const float*)d_in[9];
    const float* conv_wv = (const float*)d_in[10];
    const float* A_log   = (const float*)d_in[11];
    const float* dt_bias = (const float*)d_in[12];
    const float* norm_w  = (const float*)d_in[13];
    float* out = (float*)d_out;

    unsigned char* s = nullptr;
    cudaGetSymbolAddress((void**)&s, g_scratch);
    float*          PROJ  = (float*)(s + B_PROJ);
    __nv_bfloat16*  A3    = (__nv_bfloat16*)(s + B_A3);
    __nv_bfloat16*  B3    = (__nv_bfloat16*)(s + B_B3);
    __nv_bfloat16*  A2    = (__nv_bfloat16*)(s + B_A2);
    __nv_bfloat16*  B2    = (__nv_bfloat16*)(s + B_B2);
    float*          Qb    = (float*)(s + B_Q);
    float*          Kb    = (float*)(s + B_K);
    float*          Vb    = (float*)(s + B_V);
    float*          Ob    = (float*)(s + B_O);
    float*          Gb    = (float*)(s + B_G);
    float*          Bb    = (float*)(s + B_BB);
    float*          Cpart = (float*)(s + B_B3);   // reuse B3 after proj GEMM

    cudaFuncSetAttribute(gemm_bf16, cudaFuncAttributeMaxDynamicSharedMemorySize, GEMM_SMEM);

    split_hs<<<(T_LEN * HID) / 256, 256>>>(hs, A3);
    tsplit_proj<<<dim3(HID / 32, PROJN_PAD / 32), 256>>>(Wq, Wk, Wv, Wg, Wb, Wa, B3);
    tsplit_wo<<<dim3(VDIM / 32, HID / 32), 256>>>(Wo, B2);

    gemm_bf16<<<dim3(T_LEN / 128, PROJN_PAD / 128, 1), 256, GEMM_SMEM>>>(A3, B3, PROJ, T_LEN, PROJN_PAD, K3, K3);

    beta_g_finish<<<(T_LEN * 24 + 255) / 256, 256>>>(PROJ, A_log, dt_bias, Bb, Gb);
    conv_norm_qk<<<dim3(T_LEN, NH, 2), 128>>>(PROJ, conv_wq, conv_wk, Qb, Kb);
    conv_v_kernel<<<(T_LEN * VDIM) / 256, 256>>>(PROJ, conv_wv, Vb);

    scan_block_kernel<<<NH * 8, 256>>>(Qb, Kb, Vb, Gb, Bb, Ob);

    epilogue_kernel<<<dim3(T_LEN, NH), 256>>>(Ob, PROJ, norm_w, A2);

    gemm_bf16<<<dim3(T_LEN / 128, HID / 128, 2), 256, GEMM_SMEM>>>(A2, B2, Cpart, T_LEN, HID, K3O, K3O / 2);
    combine_kernel<<<(T_LEN * HID) / 256, 256>>>(Cpart, out);
}